// round 13
// baseline (speedup 1.0000x reference)
#include <cuda_runtime.h>
#include <cuda.h>
#include <cuda_bf16.h>
#include <math.h>
#include <stdint.h>

#if defined(__CUDA_ARCH__) && defined(__CUDA_ARCH_FEAT_SM103_ALL)
#define HAS_TCGEN05 1
#else
#define HAS_TCGEN05 0
#endif

#define BS 8
#define LL 4800
#define D 256
#define H 8
#define DH 32
#define ROWS (BS*LL)   // 38400
#define BSTRIDE (LL*D)

#define BM 128
#define BN 256
#define BK 32
// SW64 stage layout: Ahi 8K | Alo 8K | Bhi 16K | Blo 16K = 48K
#define A_HI 0
#define A_LO 8192
#define B_HI 16384
#define B_LO 32768
#define STAGE_BYTES 49152
#define SMEM_DYN (2*STAGE_BYTES + 1024)

#define ATOK 32
#define KVN (BS*H*DH*DH + BS*H*DH)

// ---------------- scratch (device globals) ----------------
__device__ float g_q   [BS*LL*D];
__device__ float g_k   [BS*LL*D];
__device__ float g_v   [BS*LL*D];
__device__ float g_qp1 [BS*LL*D];
__device__ float g_kp1 [BS*LL*D];
__device__ float g_vp1 [BS*LL*D];
__device__ float g_qp2 [BS*LL*D];
__device__ float g_kp2 [BS*LL*D];
__device__ float g_vp2 [BS*LL*D];
__device__ float g_xmid[BS*LL*D];
__device__ float g_kvz [4*KVN];

// mega buffers: 4 msg sets, 4 hcat sets, 2 t sets (contiguous)
__device__ __align__(1024) __nv_bfloat16 g_mhi[4*ROWS*D],   g_mlo[4*ROWS*D];
__device__ __align__(1024) __nv_bfloat16 g_hhi[4*ROWS*2*D], g_hlo[4*ROWS*2*D];
__device__ __align__(1024) __nv_bfloat16 g_thi[2*ROWS*2*D], g_tlo[2*ROWS*2*D];

__device__ __align__(1024) __nv_bfloat16 g_wqh[D*D],     g_wql[D*D];
__device__ __align__(1024) __nv_bfloat16 g_wkvh[2*D*D],  g_wkvl[2*D*D];   // [Wk^T ; Wv^T]
__device__ __align__(1024) __nv_bfloat16 g_wmh[D*D],     g_wml[D*D];
__device__ __align__(1024) __nv_bfloat16 g_w1h[2*D*2*D], g_w1l[2*D*2*D];
__device__ __align__(1024) __nv_bfloat16 g_w2h[D*2*D],   g_w2l[D*2*D];

// ---------------- helpers ----------------
__device__ __forceinline__ float phi(float x) { return x > 0.f ? x + 1.f : __expf(x); }
__device__ __forceinline__ uint32_t smem_u32(const void* p) {
    uint32_t a;
    asm("{ .reg .u64 t; cvta.to.shared.u64 t, %1; cvt.u32.u64 %0, t; }" : "=r"(a) : "l"(p));
    return a;
}
__device__ __forceinline__ void split_store(__nv_bfloat16* hi, __nv_bfloat16* lo,
                                            size_t idx, float v) {
    __nv_bfloat16 h = __float2bfloat16(v);
    hi[idx] = h;
    lo[idx] = __float2bfloat16(v - __bfloat162float(h));
}
__device__ __forceinline__ int off21(int l, int c) {
    int F = l * 256 + c;
    int h0 = F / 153600;
    int rem = F - h0 * 153600;
    int l0 = rem >> 5;
    return l0 * 256 + h0 * 32 + (rem & 31);
}

#if HAS_TCGEN05
__device__ __forceinline__ void mbar_init(uint32_t a, uint32_t cnt) {
    asm volatile("mbarrier.init.shared.b64 [%0], %1;" :: "r"(a), "r"(cnt) : "memory");
}
__device__ __forceinline__ void mbar_wait(uint32_t a, uint32_t parity) {
    asm volatile(
        "{\n\t.reg .pred P;\n"
        "W_%=:\n\t"
        "mbarrier.try_wait.parity.acquire.cta.shared::cta.b64 P, [%0], %1, 0x989680;\n\t"
        "@!P bra W_%=;\n\t}"
        :: "r"(a), "r"(parity) : "memory");
}
__device__ __forceinline__ void mbar_expect_tx(uint32_t a, uint32_t bytes) {
    asm volatile("mbarrier.arrive.expect_tx.shared.b64 _, [%0], %1;"
                 :: "r"(a), "r"(bytes) : "memory");
}
__device__ __forceinline__ void tma2d(uint32_t smem, const CUtensorMap* map,
                                      int x, int y, uint32_t mbar) {
    asm volatile(
        "cp.async.bulk.tensor.2d.shared::cta.global.tile.mbarrier::complete_tx::bytes "
        "[%0], [%1, {%2, %3}], [%4];"
        :: "r"(smem), "l"(map), "r"(x), "r"(y), "r"(mbar) : "memory");
}
// SW64 descriptor: layout=4, version=1 (Blackwell), SBO=32, LBO=1
__device__ __forceinline__ uint64_t make_desc64(uint32_t addr) {
    const uint64_t base = (uint64_t(4) << 61) | (uint64_t(1) << 46)
                        | (uint64_t(32) << 32) | (uint64_t(1) << 16);
    return base | ((uint64_t)(addr >> 4) & 0x3FFF);
}
__device__ __forceinline__ void mma_f16_ss(uint32_t d, uint64_t a, uint64_t b,
                                           uint32_t idesc, uint32_t en) {
    asm volatile(
        "{\n\t.reg .pred p;\n\tsetp.ne.u32 p, %5, 0;\n\t"
        "tcgen05.mma.cta_group::1.kind::f16 [%0], %1, %2, %3, {%4, %4, %4, %4}, p;\n\t}"
        :: "r"(d), "l"(a), "l"(b), "r"(idesc), "r"(0u), "r"(en) : "memory");
}
__device__ __forceinline__ void tc_commit(uint32_t mbar) {
    asm volatile(
        "tcgen05.commit.cta_group::1.mbarrier::arrive::one.shared::cluster.b64 [%0];"
        :: "r"(mbar) : "memory");
}
__device__ __forceinline__ void ldtm32(uint32_t* r, uint32_t addr) {
    asm volatile(
        "tcgen05.ld.sync.aligned.32x32b.x32.b32 "
        "{%0, %1, %2, %3, %4, %5, %6, %7, "
        " %8, %9, %10, %11, %12, %13, %14, %15, "
        " %16, %17, %18, %19, %20, %21, %22, %23, "
        " %24, %25, %26, %27, %28, %29, %30, %31}, [%32];"
        : "=r"(r[0]),  "=r"(r[1]),  "=r"(r[2]),  "=r"(r[3]),
          "=r"(r[4]),  "=r"(r[5]),  "=r"(r[6]),  "=r"(r[7]),
          "=r"(r[8]),  "=r"(r[9]),  "=r"(r[10]), "=r"(r[11]),
          "=r"(r[12]), "=r"(r[13]), "=r"(r[14]), "=r"(r[15]),
          "=r"(r[16]), "=r"(r[17]), "=r"(r[18]), "=r"(r[19]),
          "=r"(r[20]), "=r"(r[21]), "=r"(r[22]), "=r"(r[23]),
          "=r"(r[24]), "=r"(r[25]), "=r"(r[26]), "=r"(r[27]),
          "=r"(r[28]), "=r"(r[29]), "=r"(r[30]), "=r"(r[31])
        : "r"(addr));
    asm volatile("tcgen05.wait::ld.sync.aligned;" ::: "memory");
}
#endif

// ---------------- convert kernels ----------------
__global__ void __launch_bounds__(256) aconv(const float4* __restrict__ a,
                                             __nv_bfloat162* __restrict__ hi,
                                             __nv_bfloat162* __restrict__ lo, int n4) {
    int i = blockIdx.x * 256 + threadIdx.x;
    if (i >= n4) return;
    float4 v = a[i];
    __nv_bfloat16 h0 = __float2bfloat16(v.x), h1 = __float2bfloat16(v.y);
    __nv_bfloat16 h2 = __float2bfloat16(v.z), h3 = __float2bfloat16(v.w);
    hi[2*i]   = __halves2bfloat162(h0, h1);
    hi[2*i+1] = __halves2bfloat162(h2, h3);
    lo[2*i]   = __halves2bfloat162(__float2bfloat16(v.x - __bfloat162float(h0)),
                                   __float2bfloat16(v.y - __bfloat162float(h1)));
    lo[2*i+1] = __halves2bfloat162(__float2bfloat16(v.z - __bfloat162float(h2)),
                                   __float2bfloat16(v.w - __bfloat162float(h3)));
}

__global__ void __launch_bounds__(256) wconv_all(
        const float* __restrict__ Wq, const float* __restrict__ Wk,
        const float* __restrict__ Wv, const float* __restrict__ Wm,
        const float* __restrict__ W1, const float* __restrict__ W2) {
    int i = blockIdx.x * 256 + threadIdx.x;
    if (i >= 655360) return;
    const float* W; __nv_bfloat16 *hi, *lo; int K, N, li = i;
    if (li < 65536)                { W = Wq; hi = g_wqh;          lo = g_wql;          K = 256; N = 256; }
    else if ((li -= 65536) < 65536){ W = Wk; hi = g_wkvh;         lo = g_wkvl;         K = 256; N = 256; }
    else if ((li -= 65536) < 65536){ W = Wv; hi = g_wkvh + 65536; lo = g_wkvl + 65536; K = 256; N = 256; }
    else if ((li -= 65536) < 65536){ W = Wm; hi = g_wmh;          lo = g_wml;          K = 256; N = 256; }
    else if ((li -= 65536) < 262144){ W = W1; hi = g_w1h;         lo = g_w1l;          K = 512; N = 512; }
    else { li -= 262144;             W = W2; hi = g_w2h;          lo = g_w2l;          K = 512; N = 256; }
    int n = li / K, k = li % K;
    float v = W[(size_t)k * N + n];
    __nv_bfloat16 h = __float2bfloat16(v);
    hi[li] = h;
    lo[li] = __float2bfloat16(v - __bfloat162float(h));
}

// xb -> copy to dst + hcat base halves of TWO consecutive sets (pitch 512)
__global__ void __launch_bounds__(256) prep_base2(const float4* __restrict__ xb,
                                                  float4* __restrict__ dst,
                                                  __nv_bfloat16* __restrict__ hhiA,
                                                  __nv_bfloat16* __restrict__ hloA,
                                                  __nv_bfloat16* __restrict__ hhiB,
                                                  __nv_bfloat16* __restrict__ hloB) {
    int i = blockIdx.x * 256 + threadIdx.x;
    if (i >= ROWS * 64) return;
    float4 v = xb[i];
    dst[i] = v;
    int row = i >> 6, j = i & 63;
    size_t o = (size_t)row * 512 + j * 4;
    float vv[4] = {v.x, v.y, v.z, v.w};
    #pragma unroll
    for (int e = 0; e < 4; e++) {
        __nv_bfloat16 h = __float2bfloat16(vv[e]);
        __nv_bfloat16 l = __float2bfloat16(vv[e] - __bfloat162float(h));
        hhiA[o + e] = h; hloA[o + e] = l;
        hhiB[o + e] = h; hloB[o + e] = l;
    }
}

// ---------------- tcgen05 GEMM, BK=32/SW64, 2 CTAs per SM, direct epilogue ----------------
// EPI 0: fp32 -> Cf (or Cf2 when bn >= nsplit) ; EPI 1: relu -> bf16 hi/lo ;
// EPI 2: LN -> bf16 hi/lo at coff ; EPI 3: atomicAdd(Cf, 0.5*LN) with row mod rowmod
template<int EPI>
__global__ void __launch_bounds__(256, 2) tc_gemm(
        const __grid_constant__ CUtensorMap mAh, const __grid_constant__ CUtensorMap mAl,
        const __grid_constant__ CUtensorMap mBh, const __grid_constant__ CUtensorMap mBl,
        const __nv_bfloat16* __restrict__ Ahi, const __nv_bfloat16* __restrict__ Alo,
        const __nv_bfloat16* __restrict__ Bhi, const __nv_bfloat16* __restrict__ Blo,
        float* __restrict__ Cf, float* __restrict__ Cf2,
        __nv_bfloat16* __restrict__ Chi, __nv_bfloat16* __restrict__ Clo,
        const float* __restrict__ Gw, const float* __restrict__ Bw,
        int K, int ldc, int coff, int rowmod, int nsplit) {
#if HAS_TCGEN05
    extern __shared__ char dsm_raw[];
    char* sbase = (char*)(((uintptr_t)dsm_raw + 1023) & ~(uintptr_t)1023);
    __shared__ uint32_t s_tmem;
    __shared__ __align__(8) unsigned long long s_mbar[4];
    const uint32_t mb = smem_u32(s_mbar);
    const int t = threadIdx.x, wid = t >> 5, lane = t & 31;

    if (wid == 0) {
        asm volatile("tcgen05.alloc.cta_group::1.sync.aligned.shared::cta.b32 [%0], %1;"
                     :: "r"(smem_u32(&s_tmem)), "r"(256u) : "memory");
        asm volatile("tcgen05.relinquish_alloc_permit.cta_group::1.sync.aligned;");
    }
    if (t == 0) {
        mbar_init(mb, 1); mbar_init(mb + 8, 1);
        mbar_init(mb + 16, 1); mbar_init(mb + 24, 1);
    }
    __syncthreads();
    const uint32_t tmem = s_tmem;

    const int bm = blockIdx.y * BM, bn = blockIdx.x * BN;
    const int NC = K >> 5;
    const uint32_t idesc = (1u << 4) | (1u << 7) | (1u << 10)
                         | ((BN / 8) << 17) | ((BM / 16) << 24);
    const uint32_t sb32 = smem_u32(sbase);

    if (t == 0) {
        mbar_expect_tx(mb, STAGE_BYTES);
        tma2d(sb32 + A_HI, &mAh, 0, bm, mb);
        tma2d(sb32 + A_LO, &mAl, 0, bm, mb);
        tma2d(sb32 + B_HI, &mBh, 0, bn, mb);
        tma2d(sb32 + B_LO, &mBl, 0, bn, mb);
        if (NC > 1) {
            uint32_t st = sb32 + STAGE_BYTES;
            mbar_expect_tx(mb + 8, STAGE_BYTES);
            tma2d(st + A_HI, &mAh, BK, bm, mb + 8);
            tma2d(st + A_LO, &mAl, BK, bm, mb + 8);
            tma2d(st + B_HI, &mBh, BK, bn, mb + 8);
            tma2d(st + B_LO, &mBl, BK, bn, mb + 8);
        }
        int fph[2] = {0, 0}, mph[2] = {0, 0}, pend[2] = {0, 0};
        for (int c = 0; c < NC; c++) {
            const int s = c & 1;
            mbar_wait(mb + s * 8, fph[s]); fph[s] ^= 1;
            uint32_t st = sb32 + s * STAGE_BYTES;
            uint64_t dAh = make_desc64(st + A_HI), dAl = make_desc64(st + A_LO);
            uint64_t dBh = make_desc64(st + B_HI), dBl = make_desc64(st + B_LO);
            #pragma unroll
            for (int kk2 = 0; kk2 < 2; kk2++) {
                mma_f16_ss(tmem, dAh + kk2 * 2, dBh + kk2 * 2, idesc, (c > 0) || (kk2 > 0));
                mma_f16_ss(tmem, dAh + kk2 * 2, dBl + kk2 * 2, idesc, 1u);
                mma_f16_ss(tmem, dAl + kk2 * 2, dBh + kk2 * 2, idesc, 1u);
            }
            tc_commit(mb + 16 + s * 8);
            pend[s] = 1;
            if (c + 2 < NC) {
                mbar_wait(mb + 16 + s * 8, mph[s]); mph[s] ^= 1; pend[s] = 0;
                int k0 = (c + 2) * BK;
                mbar_expect_tx(mb + s * 8, STAGE_BYTES);
                tma2d(st + A_HI, &mAh, k0, bm, mb + s * 8);
                tma2d(st + A_LO, &mAl, k0, bm, mb + s * 8);
                tma2d(st + B_HI, &mBh, k0, bn, mb + s * 8);
                tma2d(st + B_LO, &mBl, k0, bn, mb + s * 8);
            }
        }
        if (pend[0]) mbar_wait(mb + 16, mph[0]);
        if (pend[1]) mbar_wait(mb + 24, mph[1]);
    }
    __syncthreads();
    asm volatile("tcgen05.fence::after_thread_sync;" ::: "memory");

    // direct register->gmem epilogue (warps 0-3; each lane owns a full row slice)
    if (wid < 4) {
        const int row = bm + wid * 32 + lane;
        float* Co = Cf;
        int bnc = bn;
        if (EPI == 0 && nsplit && bn >= nsplit) { Co = Cf2; bnc = bn - nsplit; }
        int orow = row;
        if (EPI == 3 && orow >= rowmod) orow -= rowmod;

        float mean = 0.f, rstd = 0.f;
        if (EPI >= 2) {
            float s = 0.f, s2 = 0.f;
            #pragma unroll
            for (int ch = 0; ch < 8; ch++) {
                uint32_t r[32];
                ldtm32(r, tmem + ch * 32);
                #pragma unroll
                for (int j = 0; j < 32; j++) {
                    float v = __uint_as_float(r[j]);
                    s += v; s2 += v * v;
                }
            }
            mean = s * (1.f / 256.f);
            float var = fmaf(-mean, mean, s2 * (1.f / 256.f));
            rstd = rsqrtf(var + 1e-5f);
        }
        #pragma unroll
        for (int ch = 0; ch < 8; ch++) {
            uint32_t r[32];
            ldtm32(r, tmem + ch * 32);
            float vv[32];
            #pragma unroll
            for (int j = 0; j < 32; j++) {
                float v = __uint_as_float(r[j]);
                if (EPI == 1) v = fmaxf(v, 0.f);
                if (EPI >= 2) {
                    int col = ch * 32 + j;
                    v = (v - mean) * rstd * Gw[col] + Bw[col];
                    if (EPI == 3) v *= 0.5f;
                }
                vv[j] = v;
            }
            size_t ro = (size_t)(EPI == 3 ? orow : row) * ldc + bnc + coff + ch * 32;
            if (EPI == 0) {
                #pragma unroll
                for (int j = 0; j < 32; j += 4) {
                    float4 o; o.x = vv[j]; o.y = vv[j+1]; o.z = vv[j+2]; o.w = vv[j+3];
                    *(float4*)(Co + ro + j) = o;
                }
            } else if (EPI == 3) {
                #pragma unroll
                for (int j = 0; j < 32; j++) atomicAdd(Cf + ro + j, vv[j]);
            } else {
                #pragma unroll
                for (int j = 0; j < 32; j += 2) {
                    __nv_bfloat16 h0 = __float2bfloat16(vv[j]), h1 = __float2bfloat16(vv[j+1]);
                    *(__nv_bfloat162*)(Chi + ro + j) = __halves2bfloat162(h0, h1);
                    *(__nv_bfloat162*)(Clo + ro + j) = __halves2bfloat162(
                        __float2bfloat16(vv[j]   - __bfloat162float(h0)),
                        __float2bfloat16(vv[j+1] - __bfloat162float(h1)));
                }
            }
        }
    }
    __syncthreads();
    if (wid == 0)
        asm volatile("tcgen05.dealloc.cta_group::1.sync.aligned.b32 %0, %1;"
                     :: "r"(tmem), "r"(256u));
#else
    // compile-only fallback (never runs on GB300)
    const int bm = blockIdx.y * BM, bn = blockIdx.x * BN;
    const int t = threadIdx.x;
    if (t < BM) {
        int row = bm + t;
        float vals[BN];
        for (int c = 0; c < BN; c++) {
            const __nv_bfloat16* ah = Ahi + (size_t)row * K;
            const __nv_bfloat16* al = Alo + (size_t)row * K;
            const __nv_bfloat16* bh = Bhi + (size_t)(bn + c) * K;
            const __nv_bfloat16* bl = Blo + (size_t)(bn + c) * K;
            float acc = 0.f;
            for (int kk = 0; kk < K; kk++)
                acc += (__bfloat162float(ah[kk]) + __bfloat162float(al[kk])) *
                       (__bfloat162float(bh[kk]) + __bfloat162float(bl[kk]));
            vals[c] = acc;
        }
        float mean = 0.f, rstd = 1.f;
        if (EPI >= 2) {
            float s = 0.f, s2 = 0.f;
            for (int c = 0; c < BN; c++) { s += vals[c]; s2 += vals[c] * vals[c]; }
            mean = s / BN;
            rstd = rsqrtf(s2 / BN - mean * mean + 1e-5f);
        }
        float* Co = Cf;
        int bnc = bn;
        if (EPI == 0 && nsplit && bn >= nsplit) { Co = Cf2; bnc = bn - nsplit; }
        for (int c = 0; c < BN; c++) {
            float v = vals[c];
            if (EPI == 1) v = fmaxf(v, 0.f);
            if (EPI >= 2) { v = (v - mean) * rstd * Gw[c] + Bw[c]; if (EPI == 3) v *= 0.5f; }
            int orow = row;
            if (EPI == 3 && orow >= rowmod) orow -= rowmod;
            size_t ro = (size_t)orow * ldc + bnc + coff + c;
            if (EPI == 0)      Co[ro] = v;
            else if (EPI == 3) atomicAdd(Cf + ro, v);
            else               split_store(Chi, Clo, ro, v);
        }
    }
#endif
}

// ---------------- coalesced permutes ----------------
__global__ void __launch_bounds__(256) perm13(const float* q, const float* k, const float* v,
                                              float* qd, float* kd, float* vd) {
    __shared__ float s[8][256];
    const float* S = blockIdx.z == 0 ? q : (blockIdx.z == 1 ? k : v);
    float* Dd = blockIdx.z == 0 ? qd : (blockIdx.z == 1 ? kd : vd);
    size_t rowbase = (size_t)blockIdx.x * 8;
    int t = threadIdx.x;
    #pragma unroll
    for (int i = 0; i < 8; i++) s[i][t] = S[(rowbase + i) * 256 + t];
    __syncthreads();
    int c0 = (t & 7) * 32 + (t >> 3);
    #pragma unroll
    for (int i = 0; i < 8; i++) Dd[(rowbase + i) * 256 + t] = s[i][c0];
}

__global__ void __launch_bounds__(256) perm32(const float* q, const float* k, const float* v,
                                              float* qd, float* kd, float* vd) {
    __shared__ float sm[32][33];
    const float* S = blockIdx.z == 0 ? q : (blockIdx.z == 1 ? k : v);
    float* Dd = blockIdx.z == 0 ? qd : (blockIdx.z == 1 ? kd : vd);
    int b = blockIdx.y;
    int l0b = blockIdx.x * 32;
    size_t bo = (size_t)b * BSTRIDE;
    int wr = threadIdx.x >> 5, lane = threadIdx.x & 31;
    for (int h0 = 0; h0 < H; h0++) {
        #pragma unroll
        for (int it = 0; it < 4; it++) {
            int row = wr + it * 8;
            sm[row][lane] = S[bo + (size_t)(l0b + row) * 256 + h0 * 32 + lane];
        }
        __syncthreads();
        #pragma unroll
        for (int it = 0; it < 4; it++) {
            int d0 = wr + it * 8;
            Dd[bo + (size_t)d0 * 38400 + h0 * 4800 + l0b + lane] = sm[lane][d0];
        }
        __syncthreads();
    }
}

// ---------------- mega KV reduce (4 sets via blockIdx.z) ----------------
#define KVSPLIT 10
#define KVCHUNK (LL/KVSPLIT)
__global__ void __launch_bounds__(256) kv_mega(
        const float* k0, const float* v0, const float* k1, const float* v1,
        const float* k2, const float* v2, const float* k3, const float* v3,
        float* __restrict__ kvzg, int m21mask) {
    int si = blockIdx.z;
    const float* kk = si == 0 ? k0 : si == 1 ? k1 : si == 2 ? k2 : k3;
    const float* vv = si == 0 ? v0 : si == 1 ? v1 : si == 2 ? v2 : v3;
    bool m21 = (m21mask >> si) & 1;
    float* kvz = kvzg + (size_t)si * KVN;
    int b = blockIdx.x >> 3, h = blockIdx.x & 7;
    int sbeg = blockIdx.y * KVCHUNK;
    const float* kb = kk + (size_t)b * BSTRIDE;
    const float* vb = vv + (size_t)b * BSTRIDE;
    __shared__ float ks[8][32], vs[8][32];
    int t = threadIdx.x;
    int r = t >> 5, c = t & 31;
    float acc[4] = {0.f, 0.f, 0.f, 0.f};
    float ksacc = 0.f;
    for (int s0 = sbeg; s0 < sbeg + KVCHUNK; s0 += 8) {
        int off = m21 ? off21(s0 + r, h * DH + c) : (s0 + r) * 256 + h * DH + c;
        ks[r][c] = phi(kb[off]);
        vs[r][c] = vb[off];
        __syncthreads();
        #pragma unroll
        for (int row = 0; row < 8; row++) {
            float ve = vs[row][c];
            #pragma unroll
            for (int jj = 0; jj < 4; jj++)
                acc[jj] += ks[row][r + jj * 8] * ve;
        }
        if (t < 32) {
            #pragma unroll
            for (int row = 0; row < 8; row++) ksacc += ks[row][t];
        }
        __syncthreads();
    }
    float* kvout = kvz + (size_t)(b * H + h) * DH * DH;
    #pragma unroll
    for (int jj = 0; jj < 4; jj++)
        atomicAdd(&kvout[(r + jj * 8) * DH + c], acc[jj]);
    if (t < 32) atomicAdd(&kvz[BS*H*DH*DH + (b * H + h) * DH + t], ksacc);
}

// ---------------- mega attention apply (4 sets via blockIdx.z) ----------------
__global__ void __launch_bounds__(256) attn_mega(
        const float* q0, const float* q1, const float* q2, const float* q3,
        const float* __restrict__ kvzg,
        __nv_bfloat16* __restrict__ mhig, __nv_bfloat16* __restrict__ mlog,
        int m21mask) {
    extern __shared__ float as_[];
    float* sKV = as_;
    float* sKs = sKV + H * DH * DH;
    float (*sQ)[256] = (float(*)[256])(sKs + H * DH);
    float* sZ = (float*)(sQ + ATOK);
    int si = blockIdx.z;
    const float* qsel = si == 0 ? q0 : si == 1 ? q1 : si == 2 ? q2 : q3;
    bool m21 = (m21mask >> si) & 1;
    const float* kvz = kvzg + (size_t)si * KVN;
    __nv_bfloat16* mhi = mhig + (size_t)si * ROWS * D;
    __nv_bfloat16* mlo = mlog + (size_t)si * ROWS * D;
    int b  = blockIdx.y;
    int l0 = blockIdx.x * ATOK;
    int t = threadIdx.x;
    const float* kvb = kvz + (size_t)b * H * DH * DH;
    #pragma unroll
    for (int i = t; i < H * DH * DH; i += 256) sKV[i] = kvb[i];
    if (t < H * DH) sKs[t] = kvz[BS*H*DH*DH + b * H * DH + t];
    const float* qb = qsel + (size_t)b * BSTRIDE;
    #pragma unroll
    for (int i = 0; i < ATOK; i++) {
        int off = m21 ? off21(l0 + i, t) : (l0 + i) * 256 + t;
        sQ[i][t] = phi(qb[off]);
    }
    __syncthreads();
    {
        int tok = t >> 3, h = t & 7;
        float z = 0.f;
        #pragma unroll
        for (int d = 0; d < DH; d++) z += sQ[tok][h * DH + d] * sKs[h * DH + d];
        sZ[tok * H + h] = 1.f / (z + 1e-6f);
    }
    __syncthreads();
    int c = t, h = c >> 5, e = c & 31;
    float kvreg[DH];
    #pragma unroll
    for (int d = 0; d < DH; d++) kvreg[d] = sKV[(h * DH + d) * DH + e];
    size_t base = (size_t)b * BSTRIDE + (size_t)l0 * D;
    #pragma unroll 4
    for (int jj = 0; jj < ATOK; jj++) {
        float dot = 0.f;
        #pragma unroll
        for (int d = 0; d < DH; d++)
            dot += sQ[jj][h * DH + d] * kvreg[d];
        split_store(mhi, mlo, base + (size_t)jj * D + c, dot * sZ[jj * H + h]);
    }
}

// ---------------- host orchestration ----------------
typedef CUresult (*EncFn)(CUtensorMap*, CUtensorMapDataType, cuuint32_t, void*,
        const cuuint64_t*, const cuuint64_t*, const cuuint32_t*, const cuuint32_t*,
        CUtensorMapInterleave, CUtensorMapSwizzle, CUtensorMapL2promotion,
        CUtensorMapFloatOOBfill);

extern "C" void kernel_launch(void* const* d_in, const int* in_sizes, int n_in,
                              void* d_out, int out_size) {
    (void)in_sizes; (void)n_in; (void)out_size;
    const float* x   = (const float*)d_in[0];
    const float* src = (const float*)d_in[1];
    const float* Wq  = (const float*)d_in[2];
    const float* Wk  = (const float*)d_in[3];
    const float* Wv  = (const float*)d_in[4];
    const float* Wm  = (const float*)d_in[5];
    const float* W1  = (const float*)d_in[6];
    const float* W2  = (const float*)d_in[7];
    const float* g1  = (const float*)d_in[8];
    const float* b1  = (const float*)d_in[9];
    const float* g2  = (const float*)d_in[10];
    const float* b2  = (const float*)d_in[11];
    float* out = (float*)d_out;

    float *q, *k, *v, *qp1, *kp1, *vp1, *qp2, *kp2, *vp2, *xmid, *kvz;
    cudaGetSymbolAddress((void**)&q,    g_q);
    cudaGetSymbolAddress((void**)&k,    g_k);
    cudaGetSymbolAddress((void**)&v,    g_v);
    cudaGetSymbolAddress((void**)&qp1,  g_qp1);
    cudaGetSymbolAddress((void**)&kp1,  g_kp1);
    cudaGetSymbolAddress((void**)&vp1,  g_vp1);
    cudaGetSymbolAddress((void**)&qp2,  g_qp2);
    cudaGetSymbolAddress((void**)&kp2,  g_kp2);
    cudaGetSymbolAddress((void**)&vp2,  g_vp2);
    cudaGetSymbolAddress((void**)&xmid, g_xmid);
    cudaGetSymbolAddress((void**)&kvz,  g_kvz);

    __nv_bfloat16 *mhi, *mlo, *hhi, *hlo, *thi, *tlo;
    cudaGetSymbolAddress((void**)&mhi, g_mhi); cudaGetSymbolAddress((void**)&mlo, g_mlo);
    cudaGetSymbolAddress((void**)&hhi, g_hhi); cudaGetSymbolAddress((void**)&hlo, g_hlo);
    cudaGetSymbolAddress((void**)&thi, g_thi); cudaGetSymbolAddress((void**)&tlo, g_tlo);

    __nv_bfloat16 *wqh, *wql, *wkvh, *wkvl, *wmh, *wml, *w1h, *w1l, *w2h, *w2l;
    cudaGetSymbolAddress((void**)&wqh, g_wqh);   cudaGetSymbolAddress((void**)&wql, g_wql);
    cudaGetSymbolAddress((void**)&wkvh, g_wkvh); cudaGetSymbolAddress((void**)&wkvl, g_wkvl);
    cudaGetSymbolAddress((void**)&wmh, g_wmh);   cudaGetSymbolAddress((void**)&wml, g_wml);
    cudaGetSymbolAddress((void**)&w1h, g_w1h);   cudaGetSymbolAddress((void**)&w1l, g_w1l);
    cudaGetSymbolAddress((void**)&w2h, g_w2h);   cudaGetSymbolAddress((void**)&w2l, g_w2l);

    EncFn enc = nullptr;
    {
        void* fp = nullptr;
#if CUDART_VERSION >= 12050
        cudaDriverEntryPointQueryResult qr;
        cudaGetDriverEntryPoint("cuTensorMapEncodeTiled", &fp, cudaEnableDefault, &qr);
#else
        cudaGetDriverEntryPoint("cuTensorMapEncodeTiled", &fp, cudaEnableDefault);
#endif
        enc = (EncFn)fp;
    }
    // box inner = 32 bf16 (64 B) with SWIZZLE_64B
    auto mk = [&](void* ptr, uint64_t k_elems, uint64_t rows, uint32_t boxrows) {
        CUtensorMap m{};
        cuuint64_t dims[2] = {k_elems, rows};
        cuuint64_t strides[1] = {k_elems * 2};
        cuuint32_t box[2] = {32, boxrows};
        cuuint32_t es[2] = {1, 1};
        enc(&m, CU_TENSOR_MAP_DATA_TYPE_BFLOAT16, 2, ptr, dims, strides, box, es,
            CU_TENSOR_MAP_INTERLEAVE_NONE, CU_TENSOR_MAP_SWIZZLE_64B,
            CU_TENSOR_MAP_L2_PROMOTION_L2_128B, CU_TENSOR_MAP_FLOAT_OOB_FILL_NONE);
        return m;
    };
    CUtensorMap tm_mA   = mk(mhi, 256, ROWS, 128);
    CUtensorMap tm_mAl  = mk(mlo, 256, ROWS, 128);
    CUtensorMap tm_mB   = mk(mhi + (size_t)ROWS*D, 256, ROWS, 128);
    CUtensorMap tm_mBl  = mk(mlo + (size_t)ROWS*D, 256, ROWS, 128);
    CUtensorMap tm_mall = mk(mhi, 256, 4*(uint64_t)ROWS, 128);
    CUtensorMap tm_malll= mk(mlo, 256, 4*(uint64_t)ROWS, 128);
    CUtensorMap tm_h1   = mk(hhi, 512, 2*(uint64_t)ROWS, 128);
    CUtensorMap tm_h1l  = mk(hlo, 512, 2*(uint64_t)ROWS, 128);
    CUtensorMap tm_h2   = mk(hhi + (size_t)2*ROWS*512, 512, 2*(uint64_t)ROWS, 128);
    CUtensorMap tm_h2l  = mk(hlo + (size_t)2*ROWS*512, 512, 2*(uint64_t)ROWS, 128);
    CUtensorMap tm_t    = mk(thi, 512, 2*(uint64_t)ROWS, 128);
    CUtensorMap tm_tl   = mk(tlo, 512, 2*(uint64_t)ROWS, 128);
    CUtensorMap tm_wqh = mk(wqh, 256, 256, 256), tm_wql = mk(wql, 256, 256, 256);
    CUtensorMap tm_wkv = mk(wkvh, 256, 512, 256), tm_wkvl = mk(wkvl, 256, 512, 256);
    CUtensorMap tm_wmh = mk(wmh, 256, 256, 256), tm_wml = mk(wml, 256, 256, 256);
    CUtensorMap tm_w1h = mk(w1h, 512, 512, 256), tm_w1l = mk(w1l, 512, 512, 256);
    CUtensorMap tm_w2h = mk(w2h, 512, 256, 256), tm_w2l = mk(w2l, 512, 256, 256);

    cudaFuncSetAttribute(tc_gemm<0>, cudaFuncAttributeMaxDynamicSharedMemorySize, SMEM_DYN);
    cudaFuncSetAttribute(tc_gemm<1>, cudaFuncAttributeMaxDynamicSharedMemorySize, SMEM_DYN);
    cudaFuncSetAttribute(tc_gemm<2>, cudaFuncAttributeMaxDynamicSharedMemorySize, SMEM_DYN);
    cudaFuncSetAttribute(tc_gemm<3>, cudaFuncAttributeMaxDynamicSharedMemorySize, SMEM_DYN);
    const int ATTN_SMEM = (H*DH*DH + H*DH + ATOK*256 + ATOK*H) * 4;
    cudaFuncSetAttribute(attn_mega, cudaFuncAttributeMaxDynamicSharedMemorySize, ATTN_SMEM);

    static cudaStream_t s1 = nullptr, s2 = nullptr;
    static cudaEvent_t ev[8];
    if (!s1) {
        cudaStreamCreateWithFlags(&s1, cudaStreamNonBlocking);
        cudaStreamCreateWithFlags(&s2, cudaStreamNonBlocking);
        for (int i = 0; i < 8; i++)
            cudaEventCreateWithFlags(&ev[i], cudaEventDisableTiming);
    }
    cudaEvent_t evW = ev[0], evQ = ev[1], evKV = ev[2], evP13 = ev[3], evP32 = ev[4];

    dim3 thr(256);

    wconv_all<<<2560, thr>>>(Wq, Wk, Wv, Wm, W1, W2);
    cudaEventRecord(evW, 0);
    prep_base2<<<ROWS*64/256, thr>>>((const float4*)x, (float4*)xmid,
            hhi, hlo, hhi + (size_t)ROWS*512, hlo + (size_t)ROWS*512);
    cudaStreamWaitEvent(s1, evW, 0);
    cudaStreamWaitEvent(s2, evW, 0);

    // s1: aconv(x into m set0) + Wq
    aconv<<<ROWS*D/4/256, thr, 0, s1>>>((const float4*)x,
            (__nv_bfloat162*)mhi, (__nv_bfloat162*)mlo, ROWS*D/4);
    tc_gemm<0><<<dim3(1, ROWS/BM), thr, SMEM_DYN, s1>>>(tm_mA, tm_mAl, tm_wqh, tm_wql,
            mhi, mlo, wqh, wql, q, nullptr, nullptr, nullptr, nullptr, nullptr,
            D, D, 0, 0, 0);
    cudaEventRecord(evQ, s1);

    // s2: aconv(src into m set1) + merged Wk|Wv
    aconv<<<ROWS*D/4/256, thr, 0, s2>>>((const float4*)src,
            (__nv_bfloat162*)(mhi + (size_t)ROWS*D), (__nv_bfloat162*)(mlo + (size_t)ROWS*D),
            ROWS*D/4);
    tc_gemm<0><<<dim3(2, ROWS/BM), thr, SMEM_DYN, s2>>>(tm_mB, tm_mBl, tm_wkv, tm_wkvl,
            mhi + (size_t)ROWS*D, mlo + (size_t)ROWS*D, wkvh, wkvl,
            k, v, nullptr, nullptr, nullptr, nullptr, D, D, 0, 0, 256);
    cudaEventRecord(evKV, s2);

    // perms: s1 does perm13 (needs k,v), s2 does perm32 (needs q)
    cudaStreamWaitEvent(s1, evKV, 0);
    perm13<<<dim3(ROWS/8, 1, 3), thr, 0, s1>>>(q, k, v, qp1, kp1, vp1);
    cudaEventRecord(evP13, s1);
    cudaStreamWaitEvent(s2, evQ, 0);
    perm32<<<dim3(150, BS, 3), thr, 0, s2>>>(q, k, v, qp2, kp2, vp2);
    cudaEventRecord(evP32, s2);

    // main: mega attention for all 4 sets
    cudaStreamWaitEvent(0, evP13, 0);
    cudaStreamWaitEvent(0, evP32, 0);
    cudaMemsetAsync(kvz, 0, (size_t)4 * KVN * sizeof(float));
    kv_mega<<<dim3(BS*H, KVSPLIT, 4), thr>>>(k, v, kp1, vp1, k, v, kp2, vp2, kvz, 0x4);
    attn_mega<<<dim3(LL/ATOK, BS, 4), thr, ATTN_SMEM>>>(q, qp1, q, qp2, kvz, mhi, mlo, 0x4);
    tc_gemm<2><<<dim3(1, 4*ROWS/BM), thr, SMEM_DYN>>>(tm_mall, tm_malll, tm_wmh, tm_wml,
            mhi, mlo, wmh, wml, nullptr, nullptr, hhi, hlo, g1, b1, D, 2*D, D, 0, 0);

    // phase 1 MLP (sets 0,1) -> xmid
    tc_gemm<1><<<dim3(2, 2*ROWS/BM), thr, SMEM_DYN>>>(tm_h1, tm_h1l, tm_w1h, tm_w1l,
            hhi, hlo, w1h, w1l, nullptr, nullptr, thi, tlo, nullptr, nullptr,
            2*D, 2*D, 0, 0, 0);
    tc_gemm<3><<<dim3(1, 2*ROWS/BM), thr, SMEM_DYN>>>(tm_t, tm_tl, tm_w2h, tm_w2l,
            thi, tlo, w2h, w2l, xmid, nullptr, nullptr, nullptr, g2, b2,
            2*D, D, 0, ROWS, 0);

    // prep2: out = xmid; hcat base halves of sets 2,3
    prep_base2<<<ROWS*64/256, thr>>>((const float4*)xmid, (float4*)out,
            hhi + (size_t)2*ROWS*512, hlo + (size_t)2*ROWS*512,
            hhi + (size_t)3*ROWS*512, hlo + (size_t)3*ROWS*512);

    // phase 2 MLP (sets 2,3) -> out
    tc_gemm<1><<<dim3(2, 2*ROWS/BM), thr, SMEM_DYN>>>(tm_h2, tm_h2l, tm_w1h, tm_w1l,
            hhi + (size_t)2*ROWS*512, hlo + (size_t)2*ROWS*512, w1h, w1l,
            nullptr, nullptr, thi, tlo, nullptr, nullptr, 2*D, 2*D, 0, 0, 0);
    tc_gemm<3><<<dim3(1, 2*ROWS/BM), thr, SMEM_DYN>>>(tm_t, tm_tl, tm_w2h, tm_w2l,
            thi, tlo, w2h, w2l, out, nullptr, nullptr, nullptr, g2, b2,
            2*D, D, 0, ROWS, 0);
}

// round 14
// speedup vs baseline: 1.5903x; 1.5903x over previous
#include <cuda_runtime.h>
#include <cuda.h>
#include <cuda_bf16.h>
#include <math.h>
#include <stdint.h>

#if defined(__CUDA_ARCH__) && defined(__CUDA_ARCH_FEAT_SM103_ALL)
#define HAS_TCGEN05 1
#else
#define HAS_TCGEN05 0
#endif

#define BS 8
#define LL 4800
#define D 256
#define H 8
#define DH 32
#define ROWS (BS*LL)   // 38400
#define BSTRIDE (LL*D)

#define BM 128
#define BN 256
#define BK 32
// SW64 stage layout: Ahi 8K | Alo 8K | Bhi 16K | Blo 16K = 48K
#define A_HI 0
#define A_LO 8192
#define B_HI 16384
#define B_LO 32768
#define STAGE_BYTES 49152
#define SMEM_DYN (2*STAGE_BYTES + 1024)

#define ATOK 32
#define KVN (BS*H*DH*DH + BS*H*DH)

// ---------------- scratch (device globals) ----------------
__device__ float g_q   [BS*LL*D];
__device__ float g_k   [BS*LL*D];
__device__ float g_v   [BS*LL*D];
__device__ float g_qp1 [BS*LL*D];
__device__ float g_kp1 [BS*LL*D];
__device__ float g_vp1 [BS*LL*D];
__device__ float g_qp2 [BS*LL*D];
__device__ float g_kp2 [BS*LL*D];
__device__ float g_vp2 [BS*LL*D];
__device__ float g_xmid[BS*LL*D];
__device__ float g_kvz [4*KVN];

// mega buffers: 4 msg sets, 4 hcat sets, 2 t sets (contiguous)
__device__ __align__(1024) __nv_bfloat16 g_mhi[4*ROWS*D],   g_mlo[4*ROWS*D];
__device__ __align__(1024) __nv_bfloat16 g_hhi[4*ROWS*2*D], g_hlo[4*ROWS*2*D];
__device__ __align__(1024) __nv_bfloat16 g_thi[2*ROWS*2*D], g_tlo[2*ROWS*2*D];

__device__ __align__(1024) __nv_bfloat16 g_wqh[D*D],     g_wql[D*D];
__device__ __align__(1024) __nv_bfloat16 g_wkvh[2*D*D],  g_wkvl[2*D*D];   // [Wk^T ; Wv^T]
__device__ __align__(1024) __nv_bfloat16 g_wmh[D*D],     g_wml[D*D];
__device__ __align__(1024) __nv_bfloat16 g_w1h[2*D*2*D], g_w1l[2*D*2*D];
__device__ __align__(1024) __nv_bfloat16 g_w2h[D*2*D],   g_w2l[D*2*D];

// ---------------- helpers ----------------
__device__ __forceinline__ float phi(float x) { return x > 0.f ? x + 1.f : __expf(x); }
__device__ __forceinline__ uint32_t smem_u32(const void* p) {
    uint32_t a;
    asm("{ .reg .u64 t; cvta.to.shared.u64 t, %1; cvt.u32.u64 %0, t; }" : "=r"(a) : "l"(p));
    return a;
}
__device__ __forceinline__ void split_store(__nv_bfloat16* hi, __nv_bfloat16* lo,
                                            size_t idx, float v) {
    __nv_bfloat16 h = __float2bfloat16(v);
    hi[idx] = h;
    lo[idx] = __float2bfloat16(v - __bfloat162float(h));
}
__device__ __forceinline__ int off21(int l, int c) {
    int F = l * 256 + c;
    int h0 = F / 153600;
    int rem = F - h0 * 153600;
    int l0 = rem >> 5;
    return l0 * 256 + h0 * 32 + (rem & 31);
}

#if HAS_TCGEN05
__device__ __forceinline__ void mbar_init(uint32_t a, uint32_t cnt) {
    asm volatile("mbarrier.init.shared.b64 [%0], %1;" :: "r"(a), "r"(cnt) : "memory");
}
__device__ __forceinline__ void mbar_wait(uint32_t a, uint32_t parity) {
    asm volatile(
        "{\n\t.reg .pred P;\n"
        "W_%=:\n\t"
        "mbarrier.try_wait.parity.acquire.cta.shared::cta.b64 P, [%0], %1, 0x989680;\n\t"
        "@!P bra W_%=;\n\t}"
        :: "r"(a), "r"(parity) : "memory");
}
__device__ __forceinline__ void mbar_expect_tx(uint32_t a, uint32_t bytes) {
    asm volatile("mbarrier.arrive.expect_tx.shared.b64 _, [%0], %1;"
                 :: "r"(a), "r"(bytes) : "memory");
}
__device__ __forceinline__ void tma2d(uint32_t smem, const CUtensorMap* map,
                                      int x, int y, uint32_t mbar) {
    asm volatile(
        "cp.async.bulk.tensor.2d.shared::cta.global.tile.mbarrier::complete_tx::bytes "
        "[%0], [%1, {%2, %3}], [%4];"
        :: "r"(smem), "l"(map), "r"(x), "r"(y), "r"(mbar) : "memory");
}
// SW64 descriptor: layout=4, version=1 (Blackwell), SBO=32, LBO=1
__device__ __forceinline__ uint64_t make_desc64(uint32_t addr) {
    const uint64_t base = (uint64_t(4) << 61) | (uint64_t(1) << 46)
                        | (uint64_t(32) << 32) | (uint64_t(1) << 16);
    return base | ((uint64_t)(addr >> 4) & 0x3FFF);
}
__device__ __forceinline__ void mma_f16_ss(uint32_t d, uint64_t a, uint64_t b,
                                           uint32_t idesc, uint32_t en) {
    asm volatile(
        "{\n\t.reg .pred p;\n\tsetp.ne.u32 p, %5, 0;\n\t"
        "tcgen05.mma.cta_group::1.kind::f16 [%0], %1, %2, %3, {%4, %4, %4, %4}, p;\n\t}"
        :: "r"(d), "l"(a), "l"(b), "r"(idesc), "r"(0u), "r"(en) : "memory");
}
__device__ __forceinline__ void tc_commit(uint32_t mbar) {
    asm volatile(
        "tcgen05.commit.cta_group::1.mbarrier::arrive::one.shared::cluster.b64 [%0];"
        :: "r"(mbar) : "memory");
}
__device__ __forceinline__ void ldtm32(uint32_t* r, uint32_t addr) {
    asm volatile(
        "tcgen05.ld.sync.aligned.32x32b.x32.b32 "
        "{%0, %1, %2, %3, %4, %5, %6, %7, "
        " %8, %9, %10, %11, %12, %13, %14, %15, "
        " %16, %17, %18, %19, %20, %21, %22, %23, "
        " %24, %25, %26, %27, %28, %29, %30, %31}, [%32];"
        : "=r"(r[0]),  "=r"(r[1]),  "=r"(r[2]),  "=r"(r[3]),
          "=r"(r[4]),  "=r"(r[5]),  "=r"(r[6]),  "=r"(r[7]),
          "=r"(r[8]),  "=r"(r[9]),  "=r"(r[10]), "=r"(r[11]),
          "=r"(r[12]), "=r"(r[13]), "=r"(r[14]), "=r"(r[15]),
          "=r"(r[16]), "=r"(r[17]), "=r"(r[18]), "=r"(r[19]),
          "=r"(r[20]), "=r"(r[21]), "=r"(r[22]), "=r"(r[23]),
          "=r"(r[24]), "=r"(r[25]), "=r"(r[26]), "=r"(r[27]),
          "=r"(r[28]), "=r"(r[29]), "=r"(r[30]), "=r"(r[31])
        : "r"(addr));
    asm volatile("tcgen05.wait::ld.sync.aligned;" ::: "memory");
}
#endif

// ---------------- convert kernels ----------------
__global__ void __launch_bounds__(256) aconv(const float4* __restrict__ a,
                                             __nv_bfloat162* __restrict__ hi,
                                             __nv_bfloat162* __restrict__ lo, int n4) {
    int i = blockIdx.x * 256 + threadIdx.x;
    if (i >= n4) return;
    float4 v = a[i];
    __nv_bfloat16 h0 = __float2bfloat16(v.x), h1 = __float2bfloat16(v.y);
    __nv_bfloat16 h2 = __float2bfloat16(v.z), h3 = __float2bfloat16(v.w);
    hi[2*i]   = __halves2bfloat162(h0, h1);
    hi[2*i+1] = __halves2bfloat162(h2, h3);
    lo[2*i]   = __halves2bfloat162(__float2bfloat16(v.x - __bfloat162float(h0)),
                                   __float2bfloat16(v.y - __bfloat162float(h1)));
    lo[2*i+1] = __halves2bfloat162(__float2bfloat16(v.z - __bfloat162float(h2)),
                                   __float2bfloat16(v.w - __bfloat162float(h3)));
}

__global__ void __launch_bounds__(256) wconv_all(
        const float* __restrict__ Wq, const float* __restrict__ Wk,
        const float* __restrict__ Wv, const float* __restrict__ Wm,
        const float* __restrict__ W1, const float* __restrict__ W2) {
    int i = blockIdx.x * 256 + threadIdx.x;
    if (i >= 655360) return;
    const float* W; __nv_bfloat16 *hi, *lo; int K, N, li = i;
    if (li < 65536)                { W = Wq; hi = g_wqh;          lo = g_wql;          K = 256; N = 256; }
    else if ((li -= 65536) < 65536){ W = Wk; hi = g_wkvh;         lo = g_wkvl;         K = 256; N = 256; }
    else if ((li -= 65536) < 65536){ W = Wv; hi = g_wkvh + 65536; lo = g_wkvl + 65536; K = 256; N = 256; }
    else if ((li -= 65536) < 65536){ W = Wm; hi = g_wmh;          lo = g_wml;          K = 256; N = 256; }
    else if ((li -= 65536) < 262144){ W = W1; hi = g_w1h;         lo = g_w1l;          K = 512; N = 512; }
    else { li -= 262144;             W = W2; hi = g_w2h;          lo = g_w2l;          K = 512; N = 256; }
    int n = li / K, k = li % K;
    float v = W[(size_t)k * N + n];
    __nv_bfloat16 h = __float2bfloat16(v);
    hi[li] = h;
    lo[li] = __float2bfloat16(v - __bfloat162float(h));
}

// xb -> copy to dst + hcat base halves of TWO consecutive sets (pitch 512)
__global__ void __launch_bounds__(256) prep_base2(const float4* __restrict__ xb,
                                                  float4* __restrict__ dst,
                                                  __nv_bfloat16* __restrict__ hhiA,
                                                  __nv_bfloat16* __restrict__ hloA,
                                                  __nv_bfloat16* __restrict__ hhiB,
                                                  __nv_bfloat16* __restrict__ hloB) {
    int i = blockIdx.x * 256 + threadIdx.x;
    if (i >= ROWS * 64) return;
    float4 v = xb[i];
    dst[i] = v;
    int row = i >> 6, j = i & 63;
    size_t o = (size_t)row * 512 + j * 4;
    float vv[4] = {v.x, v.y, v.z, v.w};
    #pragma unroll
    for (int e = 0; e < 4; e++) {
        __nv_bfloat16 h = __float2bfloat16(vv[e]);
        __nv_bfloat16 l = __float2bfloat16(vv[e] - __bfloat162float(h));
        hhiA[o + e] = h; hloA[o + e] = l;
        hhiB[o + e] = h; hloB[o + e] = l;
    }
}

// ---------------- tcgen05 GEMM, BK=32/SW64, 2 CTAs/SM, smem-staged epilogue ----------------
// EPI 0: fp32 -> Cf (or Cf2 when bn >= nsplit) ; EPI 1: relu -> bf16 hi/lo ;
// EPI 2: LN -> bf16 hi/lo at coff ; EPI 3: atomicAdd(Cf, 0.5*LN) with row mod rowmod
template<int EPI>
__global__ void __launch_bounds__(256, 2) tc_gemm(
        const __grid_constant__ CUtensorMap mAh, const __grid_constant__ CUtensorMap mAl,
        const __grid_constant__ CUtensorMap mBh, const __grid_constant__ CUtensorMap mBl,
        const __nv_bfloat16* __restrict__ Ahi, const __nv_bfloat16* __restrict__ Alo,
        const __nv_bfloat16* __restrict__ Bhi, const __nv_bfloat16* __restrict__ Blo,
        float* __restrict__ Cf, float* __restrict__ Cf2,
        __nv_bfloat16* __restrict__ Chi, __nv_bfloat16* __restrict__ Clo,
        const float* __restrict__ Gw, const float* __restrict__ Bw,
        int K, int ldc, int coff, int rowmod, int nsplit) {
#if HAS_TCGEN05
    extern __shared__ char dsm_raw[];
    char* sbase = (char*)(((uintptr_t)dsm_raw + 1023) & ~(uintptr_t)1023);
    __shared__ uint32_t s_tmem;
    __shared__ __align__(8) unsigned long long s_mbar[4];
    const uint32_t mb = smem_u32(s_mbar);
    const int t = threadIdx.x, wid = t >> 5, lane = t & 31;

    if (wid == 0) {
        asm volatile("tcgen05.alloc.cta_group::1.sync.aligned.shared::cta.b32 [%0], %1;"
                     :: "r"(smem_u32(&s_tmem)), "r"(256u) : "memory");
        asm volatile("tcgen05.relinquish_alloc_permit.cta_group::1.sync.aligned;");
    }
    if (t == 0) {
        mbar_init(mb, 1); mbar_init(mb + 8, 1);
        mbar_init(mb + 16, 1); mbar_init(mb + 24, 1);
    }
    __syncthreads();
    const uint32_t tmem = s_tmem;

    const int bm = blockIdx.y * BM, bn = blockIdx.x * BN;
    const int NC = K >> 5;
    const uint32_t idesc = (1u << 4) | (1u << 7) | (1u << 10)
                         | ((BN / 8) << 17) | ((BM / 16) << 24);
    const uint32_t sb32 = smem_u32(sbase);

    if (t == 0) {
        mbar_expect_tx(mb, STAGE_BYTES);
        tma2d(sb32 + A_HI, &mAh, 0, bm, mb);
        tma2d(sb32 + A_LO, &mAl, 0, bm, mb);
        tma2d(sb32 + B_HI, &mBh, 0, bn, mb);
        tma2d(sb32 + B_LO, &mBl, 0, bn, mb);
        if (NC > 1) {
            uint32_t st = sb32 + STAGE_BYTES;
            mbar_expect_tx(mb + 8, STAGE_BYTES);
            tma2d(st + A_HI, &mAh, BK, bm, mb + 8);
            tma2d(st + A_LO, &mAl, BK, bm, mb + 8);
            tma2d(st + B_HI, &mBh, BK, bn, mb + 8);
            tma2d(st + B_LO, &mBl, BK, bn, mb + 8);
        }
        int fph[2] = {0, 0}, mph[2] = {0, 0}, pend[2] = {0, 0};
        for (int c = 0; c < NC; c++) {
            const int s = c & 1;
            mbar_wait(mb + s * 8, fph[s]); fph[s] ^= 1;
            uint32_t st = sb32 + s * STAGE_BYTES;
            uint64_t dAh = make_desc64(st + A_HI), dAl = make_desc64(st + A_LO);
            uint64_t dBh = make_desc64(st + B_HI), dBl = make_desc64(st + B_LO);
            #pragma unroll
            for (int kk2 = 0; kk2 < 2; kk2++) {
                mma_f16_ss(tmem, dAh + kk2 * 2, dBh + kk2 * 2, idesc, (c > 0) || (kk2 > 0));
                mma_f16_ss(tmem, dAh + kk2 * 2, dBl + kk2 * 2, idesc, 1u);
                mma_f16_ss(tmem, dAl + kk2 * 2, dBh + kk2 * 2, idesc, 1u);
            }
            tc_commit(mb + 16 + s * 8);
            pend[s] = 1;
            if (c + 2 < NC) {
                mbar_wait(mb + 16 + s * 8, mph[s]); mph[s] ^= 1; pend[s] = 0;
                int k0 = (c + 2) * BK;
                mbar_expect_tx(mb + s * 8, STAGE_BYTES);
                tma2d(st + A_HI, &mAh, k0, bm, mb + s * 8);
                tma2d(st + A_LO, &mAl, k0, bm, mb + s * 8);
                tma2d(st + B_HI, &mBh, k0, bn, mb + s * 8);
                tma2d(st + B_LO, &mBl, k0, bn, mb + s * 8);
            }
        }
        if (pend[0]) mbar_wait(mb + 16, mph[0]);
        if (pend[1]) mbar_wait(mb + 24, mph[1]);
    }
    __syncthreads();
    asm volatile("tcgen05.fence::after_thread_sync;" ::: "memory");

    // smem-staged, coalesced epilogue (R12-proven)
    float* Co = Cf;
    int bnc = bn;
    if (EPI == 0 && nsplit && bn >= nsplit) { Co = Cf2; bnc = bn - nsplit; }

    float (*tile)[33] = (float(*)[33])sbase;
    float mean = 0.f, rstd = 0.f;
    if (EPI >= 2 && wid < 4) {
        float s = 0.f, s2 = 0.f;
        #pragma unroll
        for (int ch = 0; ch < 8; ch++) {
            uint32_t r[32];
            ldtm32(r, tmem + ch * 32);
            #pragma unroll
            for (int j = 0; j < 32; j++) {
                float v = __uint_as_float(r[j]);
                s += v; s2 += v * v;
            }
        }
        mean = s * (1.f / 256.f);
        float var = fmaf(-mean, mean, s2 * (1.f / 256.f));
        rstd = rsqrtf(var + 1e-5f);
    }
    #pragma unroll
    for (int ch = 0; ch < 8; ch++) {
        if (wid < 4) {
            uint32_t r[32];
            ldtm32(r, tmem + ch * 32);
            int rloc = wid * 32 + lane;
            #pragma unroll
            for (int j = 0; j < 32; j++) {
                float v = __uint_as_float(r[j]);
                if (EPI == 1) v = fmaxf(v, 0.f);
                if (EPI >= 2) {
                    int col = ch * 32 + j;
                    v = (v - mean) * rstd * Gw[col] + Bw[col];
                    if (EPI == 3) v *= 0.5f;
                }
                tile[rloc][j] = v;
            }
        }
        __syncthreads();
        #pragma unroll
        for (int i = 0; i < 16; i++) {
            int idx = i * 256 + t;
            int rr = idx >> 5, cc = idx & 31;
            float v = tile[rr][cc];
            int orow = bm + rr;
            if (EPI == 3 && orow >= rowmod) orow -= rowmod;
            size_t ro = (size_t)orow * ldc + bnc + coff + ch * 32 + cc;
            if (EPI == 0)       Co[ro] = v;
            else if (EPI == 3)  atomicAdd(Cf + ro, v);
            else                split_store(Chi, Clo, ro, v);
        }
        __syncthreads();
    }
    if (wid == 0)
        asm volatile("tcgen05.dealloc.cta_group::1.sync.aligned.b32 %0, %1;"
                     :: "r"(tmem), "r"(256u));
#else
    // compile-only fallback (never runs on GB300)
    const int bm = blockIdx.y * BM, bn = blockIdx.x * BN;
    const int t = threadIdx.x;
    if (t < BM) {
        int row = bm + t;
        float vals[BN];
        for (int c = 0; c < BN; c++) {
            const __nv_bfloat16* ah = Ahi + (size_t)row * K;
            const __nv_bfloat16* al = Alo + (size_t)row * K;
            const __nv_bfloat16* bh = Bhi + (size_t)(bn + c) * K;
            const __nv_bfloat16* bl = Blo + (size_t)(bn + c) * K;
            float acc = 0.f;
            for (int kk = 0; kk < K; kk++)
                acc += (__bfloat162float(ah[kk]) + __bfloat162float(al[kk])) *
                       (__bfloat162float(bh[kk]) + __bfloat162float(bl[kk]));
            vals[c] = acc;
        }
        float mean = 0.f, rstd = 1.f;
        if (EPI >= 2) {
            float s = 0.f, s2 = 0.f;
            for (int c = 0; c < BN; c++) { s += vals[c]; s2 += vals[c] * vals[c]; }
            mean = s / BN;
            rstd = rsqrtf(s2 / BN - mean * mean + 1e-5f);
        }
        float* Co = Cf;
        int bnc = bn;
        if (EPI == 0 && nsplit && bn >= nsplit) { Co = Cf2; bnc = bn - nsplit; }
        for (int c = 0; c < BN; c++) {
            float v = vals[c];
            if (EPI == 1) v = fmaxf(v, 0.f);
            if (EPI >= 2) { v = (v - mean) * rstd * Gw[c] + Bw[c]; if (EPI == 3) v *= 0.5f; }
            int orow = row;
            if (EPI == 3 && orow >= rowmod) orow -= rowmod;
            size_t ro = (size_t)orow * ldc + bnc + coff + c;
            if (EPI == 0)      Co[ro] = v;
            else if (EPI == 3) atomicAdd(Cf + ro, v);
            else               split_store(Chi, Clo, ro, v);
        }
    }
#endif
}

// ---------------- coalesced permutes ----------------
__global__ void __launch_bounds__(256) perm13(const float* q, const float* k, const float* v,
                                              float* qd, float* kd, float* vd) {
    __shared__ float s[8][256];
    const float* S = blockIdx.z == 0 ? q : (blockIdx.z == 1 ? k : v);
    float* Dd = blockIdx.z == 0 ? qd : (blockIdx.z == 1 ? kd : vd);
    size_t rowbase = (size_t)blockIdx.x * 8;
    int t = threadIdx.x;
    #pragma unroll
    for (int i = 0; i < 8; i++) s[i][t] = S[(rowbase + i) * 256 + t];
    __syncthreads();
    int c0 = (t & 7) * 32 + (t >> 3);
    #pragma unroll
    for (int i = 0; i < 8; i++) Dd[(rowbase + i) * 256 + t] = s[i][c0];
}

__global__ void __launch_bounds__(256) perm32(const float* q, const float* k, const float* v,
                                              float* qd, float* kd, float* vd) {
    __shared__ float sm[32][33];
    const float* S = blockIdx.z == 0 ? q : (blockIdx.z == 1 ? k : v);
    float* Dd = blockIdx.z == 0 ? qd : (blockIdx.z == 1 ? kd : vd);
    int b = blockIdx.y;
    int l0b = blockIdx.x * 32;
    size_t bo = (size_t)b * BSTRIDE;
    int wr = threadIdx.x >> 5, lane = threadIdx.x & 31;
    for (int h0 = 0; h0 < H; h0++) {
        #pragma unroll
        for (int it = 0; it < 4; it++) {
            int row = wr + it * 8;
            sm[row][lane] = S[bo + (size_t)(l0b + row) * 256 + h0 * 32 + lane];
        }
        __syncthreads();
        #pragma unroll
        for (int it = 0; it < 4; it++) {
            int d0 = wr + it * 8;
            Dd[bo + (size_t)d0 * 38400 + h0 * 4800 + l0b + lane] = sm[lane][d0];
        }
        __syncthreads();
    }
}

// ---------------- mega KV reduce (4 sets via blockIdx.z) ----------------
#define KVSPLIT 10
#define KVCHUNK (LL/KVSPLIT)
__global__ void __launch_bounds__(256) kv_mega(
        const float* k0, const float* v0, const float* k1, const float* v1,
        const float* k2, const float* v2, const float* k3, const float* v3,
        float* __restrict__ kvzg, int m21mask) {
    int si = blockIdx.z;
    const float* kk = si == 0 ? k0 : si == 1 ? k1 : si == 2 ? k2 : k3;
    const float* vv = si == 0 ? v0 : si == 1 ? v1 : si == 2 ? v2 : v3;
    bool m21 = (m21mask >> si) & 1;
    float* kvz = kvzg + (size_t)si * KVN;
    int b = blockIdx.x >> 3, h = blockIdx.x & 7;
    int sbeg = blockIdx.y * KVCHUNK;
    const float* kb = kk + (size_t)b * BSTRIDE;
    const float* vb = vv + (size_t)b * BSTRIDE;
    __shared__ float ks[8][32], vs[8][32];
    int t = threadIdx.x;
    int r = t >> 5, c = t & 31;
    float acc[4] = {0.f, 0.f, 0.f, 0.f};
    float ksacc = 0.f;
    for (int s0 = sbeg; s0 < sbeg + KVCHUNK; s0 += 8) {
        int off = m21 ? off21(s0 + r, h * DH + c) : (s0 + r) * 256 + h * DH + c;
        ks[r][c] = phi(kb[off]);
        vs[r][c] = vb[off];
        __syncthreads();
        #pragma unroll
        for (int row = 0; row < 8; row++) {
            float ve = vs[row][c];
            #pragma unroll
            for (int jj = 0; jj < 4; jj++)
                acc[jj] += ks[row][r + jj * 8] * ve;
        }
        if (t < 32) {
            #pragma unroll
            for (int row = 0; row < 8; row++) ksacc += ks[row][t];
        }
        __syncthreads();
    }
    float* kvout = kvz + (size_t)(b * H + h) * DH * DH;
    #pragma unroll
    for (int jj = 0; jj < 4; jj++)
        atomicAdd(&kvout[(r + jj * 8) * DH + c], acc[jj]);
    if (t < 32) atomicAdd(&kvz[BS*H*DH*DH + (b * H + h) * DH + t], ksacc);
}

// ---------------- mega attention apply (4 sets via blockIdx.z) ----------------
__global__ void __launch_bounds__(256) attn_mega(
        const float* q0, const float* q1, const float* q2, const float* q3,
        const float* __restrict__ kvzg,
        __nv_bfloat16* __restrict__ mhig, __nv_bfloat16* __restrict__ mlog,
        int m21mask) {
    extern __shared__ float as_[];
    float* sKV = as_;
    float* sKs = sKV + H * DH * DH;
    float (*sQ)[256] = (float(*)[256])(sKs + H * DH);
    float* sZ = (float*)(sQ + ATOK);
    int si = blockIdx.z;
    const float* qsel = si == 0 ? q0 : si == 1 ? q1 : si == 2 ? q2 : q3;
    bool m21 = (m21mask >> si) & 1;
    const float* kvz = kvzg + (size_t)si * KVN;
    __nv_bfloat16* mhi = mhig + (size_t)si * ROWS * D;
    __nv_bfloat16* mlo = mlog + (size_t)si * ROWS * D;
    int b  = blockIdx.y;
    int l0 = blockIdx.x * ATOK;
    int t = threadIdx.x;
    const float* kvb = kvz + (size_t)b * H * DH * DH;
    #pragma unroll
    for (int i = t; i < H * DH * DH; i += 256) sKV[i] = kvb[i];
    if (t < H * DH) sKs[t] = kvz[BS*H*DH*DH + b * H * DH + t];
    const float* qb = qsel + (size_t)b * BSTRIDE;
    #pragma unroll
    for (int i = 0; i < ATOK; i++) {
        int off = m21 ? off21(l0 + i, t) : (l0 + i) * 256 + t;
        sQ[i][t] = phi(qb[off]);
    }
    __syncthreads();
    {
        int tok = t >> 3, h = t & 7;
        float z = 0.f;
        #pragma unroll
        for (int d = 0; d < DH; d++) z += sQ[tok][h * DH + d] * sKs[h * DH + d];
        sZ[tok * H + h] = 1.f / (z + 1e-6f);
    }
    __syncthreads();
    int c = t, h = c >> 5, e = c & 31;
    float kvreg[DH];
    #pragma unroll
    for (int d = 0; d < DH; d++) kvreg[d] = sKV[(h * DH + d) * DH + e];
    size_t base = (size_t)b * BSTRIDE + (size_t)l0 * D;
    #pragma unroll 4
    for (int jj = 0; jj < ATOK; jj++) {
        float dot = 0.f;
        #pragma unroll
        for (int d = 0; d < DH; d++)
            dot += sQ[jj][h * DH + d] * kvreg[d];
        split_store(mhi, mlo, base + (size_t)jj * D + c, dot * sZ[jj * H + h]);
    }
}

// ---------------- host orchestration ----------------
typedef CUresult (*EncFn)(CUtensorMap*, CUtensorMapDataType, cuuint32_t, void*,
        const cuuint64_t*, const cuuint64_t*, const cuuint32_t*, const cuuint32_t*,
        CUtensorMapInterleave, CUtensorMapSwizzle, CUtensorMapL2promotion,
        CUtensorMapFloatOOBfill);

extern "C" void kernel_launch(void* const* d_in, const int* in_sizes, int n_in,
                              void* d_out, int out_size) {
    (void)in_sizes; (void)n_in; (void)out_size;
    const float* x   = (const float*)d_in[0];
    const float* src = (const float*)d_in[1];
    const float* Wq  = (const float*)d_in[2];
    const float* Wk  = (const float*)d_in[3];
    const float* Wv  = (const float*)d_in[4];
    const float* Wm  = (const float*)d_in[5];
    const float* W1  = (const float*)d_in[6];
    const float* W2  = (const float*)d_in[7];
    const float* g1  = (const float*)d_in[8];
    const float* b1  = (const float*)d_in[9];
    const float* g2  = (const float*)d_in[10];
    const float* b2  = (const float*)d_in[11];
    float* out = (float*)d_out;

    float *q, *k, *v, *qp1, *kp1, *vp1, *qp2, *kp2, *vp2, *xmid, *kvz;
    cudaGetSymbolAddress((void**)&q,    g_q);
    cudaGetSymbolAddress((void**)&k,    g_k);
    cudaGetSymbolAddress((void**)&v,    g_v);
    cudaGetSymbolAddress((void**)&qp1,  g_qp1);
    cudaGetSymbolAddress((void**)&kp1,  g_kp1);
    cudaGetSymbolAddress((void**)&vp1,  g_vp1);
    cudaGetSymbolAddress((void**)&qp2,  g_qp2);
    cudaGetSymbolAddress((void**)&kp2,  g_kp2);
    cudaGetSymbolAddress((void**)&vp2,  g_vp2);
    cudaGetSymbolAddress((void**)&xmid, g_xmid);
    cudaGetSymbolAddress((void**)&kvz,  g_kvz);

    __nv_bfloat16 *mhi, *mlo, *hhi, *hlo, *thi, *tlo;
    cudaGetSymbolAddress((void**)&mhi, g_mhi); cudaGetSymbolAddress((void**)&mlo, g_mlo);
    cudaGetSymbolAddress((void**)&hhi, g_hhi); cudaGetSymbolAddress((void**)&hlo, g_hlo);
    cudaGetSymbolAddress((void**)&thi, g_thi); cudaGetSymbolAddress((void**)&tlo, g_tlo);

    __nv_bfloat16 *wqh, *wql, *wkvh, *wkvl, *wmh, *wml, *w1h, *w1l, *w2h, *w2l;
    cudaGetSymbolAddress((void**)&wqh, g_wqh);   cudaGetSymbolAddress((void**)&wql, g_wql);
    cudaGetSymbolAddress((void**)&wkvh, g_wkvh); cudaGetSymbolAddress((void**)&wkvl, g_wkvl);
    cudaGetSymbolAddress((void**)&wmh, g_wmh);   cudaGetSymbolAddress((void**)&wml, g_wml);
    cudaGetSymbolAddress((void**)&w1h, g_w1h);   cudaGetSymbolAddress((void**)&w1l, g_w1l);
    cudaGetSymbolAddress((void**)&w2h, g_w2h);   cudaGetSymbolAddress((void**)&w2l, g_w2l);

    EncFn enc = nullptr;
    {
        void* fp = nullptr;
#if CUDART_VERSION >= 12050
        cudaDriverEntryPointQueryResult qr;
        cudaGetDriverEntryPoint("cuTensorMapEncodeTiled", &fp, cudaEnableDefault, &qr);
#else
        cudaGetDriverEntryPoint("cuTensorMapEncodeTiled", &fp, cudaEnableDefault);
#endif
        enc = (EncFn)fp;
    }
    // box inner = 32 bf16 (64 B) with SWIZZLE_64B
    auto mk = [&](void* ptr, uint64_t k_elems, uint64_t rows, uint32_t boxrows) {
        CUtensorMap m{};
        cuuint64_t dims[2] = {k_elems, rows};
        cuuint64_t strides[1] = {k_elems * 2};
        cuuint32_t box[2] = {32, boxrows};
        cuuint32_t es[2] = {1, 1};
        enc(&m, CU_TENSOR_MAP_DATA_TYPE_BFLOAT16, 2, ptr, dims, strides, box, es,
            CU_TENSOR_MAP_INTERLEAVE_NONE, CU_TENSOR_MAP_SWIZZLE_64B,
            CU_TENSOR_MAP_L2_PROMOTION_L2_128B, CU_TENSOR_MAP_FLOAT_OOB_FILL_NONE);
        return m;
    };
    CUtensorMap tm_mA   = mk(mhi, 256, ROWS, 128);
    CUtensorMap tm_mAl  = mk(mlo, 256, ROWS, 128);
    CUtensorMap tm_mB   = mk(mhi + (size_t)ROWS*D, 256, ROWS, 128);
    CUtensorMap tm_mBl  = mk(mlo + (size_t)ROWS*D, 256, ROWS, 128);
    CUtensorMap tm_mall = mk(mhi, 256, 4*(uint64_t)ROWS, 128);
    CUtensorMap tm_malll= mk(mlo, 256, 4*(uint64_t)ROWS, 128);
    CUtensorMap tm_h1   = mk(hhi, 512, 2*(uint64_t)ROWS, 128);
    CUtensorMap tm_h1l  = mk(hlo, 512, 2*(uint64_t)ROWS, 128);
    CUtensorMap tm_h2   = mk(hhi + (size_t)2*ROWS*512, 512, 2*(uint64_t)ROWS, 128);
    CUtensorMap tm_h2l  = mk(hlo + (size_t)2*ROWS*512, 512, 2*(uint64_t)ROWS, 128);
    CUtensorMap tm_t    = mk(thi, 512, 2*(uint64_t)ROWS, 128);
    CUtensorMap tm_tl   = mk(tlo, 512, 2*(uint64_t)ROWS, 128);
    CUtensorMap tm_wqh = mk(wqh, 256, 256, 256), tm_wql = mk(wql, 256, 256, 256);
    CUtensorMap tm_wkv = mk(wkvh, 256, 512, 256), tm_wkvl = mk(wkvl, 256, 512, 256);
    CUtensorMap tm_wmh = mk(wmh, 256, 256, 256), tm_wml = mk(wml, 256, 256, 256);
    CUtensorMap tm_w1h = mk(w1h, 512, 512, 256), tm_w1l = mk(w1l, 512, 512, 256);
    CUtensorMap tm_w2h = mk(w2h, 512, 256, 256), tm_w2l = mk(w2l, 512, 256, 256);

    cudaFuncSetAttribute(tc_gemm<0>, cudaFuncAttributeMaxDynamicSharedMemorySize, SMEM_DYN);
    cudaFuncSetAttribute(tc_gemm<1>, cudaFuncAttributeMaxDynamicSharedMemorySize, SMEM_DYN);
    cudaFuncSetAttribute(tc_gemm<2>, cudaFuncAttributeMaxDynamicSharedMemorySize, SMEM_DYN);
    cudaFuncSetAttribute(tc_gemm<3>, cudaFuncAttributeMaxDynamicSharedMemorySize, SMEM_DYN);
    const int ATTN_SMEM = (H*DH*DH + H*DH + ATOK*256 + ATOK*H) * 4;
    cudaFuncSetAttribute(attn_mega, cudaFuncAttributeMaxDynamicSharedMemorySize, ATTN_SMEM);

    static cudaStream_t s1 = nullptr, s2 = nullptr;
    static cudaEvent_t ev[8];
    if (!s1) {
        cudaStreamCreateWithFlags(&s1, cudaStreamNonBlocking);
        cudaStreamCreateWithFlags(&s2, cudaStreamNonBlocking);
        for (int i = 0; i < 8; i++)
            cudaEventCreateWithFlags(&ev[i], cudaEventDisableTiming);
    }
    cudaEvent_t evW = ev[0], evQ = ev[1], evKV = ev[2], evP13 = ev[3], evP32 = ev[4];

    dim3 thr(256);

    wconv_all<<<2560, thr>>>(Wq, Wk, Wv, Wm, W1, W2);
    cudaEventRecord(evW, 0);
    prep_base2<<<ROWS*64/256, thr>>>((const float4*)x, (float4*)xmid,
            hhi, hlo, hhi + (size_t)ROWS*512, hlo + (size_t)ROWS*512);
    cudaStreamWaitEvent(s1, evW, 0);
    cudaStreamWaitEvent(s2, evW, 0);

    // s1: aconv(x into m set0) + Wq
    aconv<<<ROWS*D/4/256, thr, 0, s1>>>((const float4*)x,
            (__nv_bfloat162*)mhi, (__nv_bfloat162*)mlo, ROWS*D/4);
    tc_gemm<0><<<dim3(1, ROWS/BM), thr, SMEM_DYN, s1>>>(tm_mA, tm_mAl, tm_wqh, tm_wql,
            mhi, mlo, wqh, wql, q, nullptr, nullptr, nullptr, nullptr, nullptr,
            D, D, 0, 0, 0);
    cudaEventRecord(evQ, s1);

    // s2: aconv(src into m set1) + merged Wk|Wv (one launch, nsplit routes outputs)
    aconv<<<ROWS*D/4/256, thr, 0, s2>>>((const float4*)src,
            (__nv_bfloat162*)(mhi + (size_t)ROWS*D), (__nv_bfloat162*)(mlo + (size_t)ROWS*D),
            ROWS*D/4);
    tc_gemm<0><<<dim3(2, ROWS/BM), thr, SMEM_DYN, s2>>>(tm_mB, tm_mBl, tm_wkv, tm_wkvl,
            mhi + (size_t)ROWS*D, mlo + (size_t)ROWS*D, wkvh, wkvl,
            k, v, nullptr, nullptr, nullptr, nullptr, D, D, 0, 0, 256);
    cudaEventRecord(evKV, s2);

    // perms: s1 does perm13 (needs k,v), s2 does perm32 (needs q)
    cudaStreamWaitEvent(s1, evKV, 0);
    perm13<<<dim3(ROWS/8, 1, 3), thr, 0, s1>>>(q, k, v, qp1, kp1, vp1);
    cudaEventRecord(evP13, s1);
    cudaStreamWaitEvent(s2, evQ, 0);
    perm32<<<dim3(150, BS, 3), thr, 0, s2>>>(q, k, v, qp2, kp2, vp2);
    cudaEventRecord(evP32, s2);

    // main: mega attention for all 4 sets
    cudaStreamWaitEvent(0, evP13, 0);
    cudaStreamWaitEvent(0, evP32, 0);
    cudaMemsetAsync(kvz, 0, (size_t)4 * KVN * sizeof(float));
    kv_mega<<<dim3(BS*H, KVSPLIT, 4), thr>>>(k, v, kp1, vp1, k, v, kp2, vp2, kvz, 0x4);
    attn_mega<<<dim3(LL/ATOK, BS, 4), thr, ATTN_SMEM>>>(q, qp1, q, qp2, kvz, mhi, mlo, 0x4);
    tc_gemm<2><<<dim3(1, 4*ROWS/BM), thr, SMEM_DYN>>>(tm_mall, tm_malll, tm_wmh, tm_wml,
            mhi, mlo, wmh, wml, nullptr, nullptr, hhi, hlo, g1, b1, D, 2*D, D, 0, 0);

    // phase 1 MLP (sets 0,1) -> xmid
    tc_gemm<1><<<dim3(2, 2*ROWS/BM), thr, SMEM_DYN>>>(tm_h1, tm_h1l, tm_w1h, tm_w1l,
            hhi, hlo, w1h, w1l, nullptr, nullptr, thi, tlo, nullptr, nullptr,
            2*D, 2*D, 0, 0, 0);
    tc_gemm<3><<<dim3(1, 2*ROWS/BM), thr, SMEM_DYN>>>(tm_t, tm_tl, tm_w2h, tm_w2l,
            thi, tlo, w2h, w2l, xmid, nullptr, nullptr, nullptr, g2, b2,
            2*D, D, 0, ROWS, 0);

    // prep2: out = xmid; hcat base halves of sets 2,3
    prep_base2<<<ROWS*64/256, thr>>>((const float4*)xmid, (float4*)out,
            hhi + (size_t)2*ROWS*512, hlo + (size_t)2*ROWS*512,
            hhi + (size_t)3*ROWS*512, hlo + (size_t)3*ROWS*512);

    // phase 2 MLP (sets 2,3) -> out
    tc_gemm<1><<<dim3(2, 2*ROWS/BM), thr, SMEM_DYN>>>(tm_h2, tm_h2l, tm_w1h, tm_w1l,
            hhi + (size_t)2*ROWS*512, hlo + (size_t)2*ROWS*512, w1h, w1l,
            nullptr, nullptr, thi, tlo, nullptr, nullptr, 2*D, 2*D, 0, 0, 0);
    tc_gemm<3><<<dim3(1, 2*ROWS/BM), thr, SMEM_DYN>>>(tm_t, tm_tl, tm_w2h, tm_w2l,
            thi, tlo, w2h, w2l, out, nullptr, nullptr, nullptr, g2, b2,
            2*D, D, 0, ROWS, 0);
}

// round 15
// speedup vs baseline: 1.6101x; 1.0124x over previous
#include <cuda_runtime.h>
#include <cuda.h>
#include <cuda_bf16.h>
#include <math.h>
#include <stdint.h>

#if defined(__CUDA_ARCH__) && defined(__CUDA_ARCH_FEAT_SM103_ALL)
#define HAS_TCGEN05 1
#else
#define HAS_TCGEN05 0
#endif

#define BS 8
#define LL 4800
#define D 256
#define H 8
#define DH 32
#define ROWS (BS*LL)   // 38400
#define BSTRIDE (LL*D)

#define BM 128
#define BN 256
#define BK 32
// SW64 stage layout: Ahi 8K | Alo 8K | Bhi 16K | Blo 16K = 48K
#define A_HI 0
#define A_LO 8192
#define B_HI 16384
#define B_LO 32768
#define STAGE_BYTES 49152
#define SMEM_DYN (2*STAGE_BYTES + 1024)

#define ATOK 32
#define KVN (BS*H*DH*DH + BS*H*DH)

// ---------------- scratch (device globals) ----------------
__device__ float g_q   [BS*LL*D];
__device__ float g_k   [BS*LL*D];
__device__ float g_v   [BS*LL*D];
__device__ float g_qp1 [BS*LL*D];
__device__ float g_kp1 [BS*LL*D];
__device__ float g_vp1 [BS*LL*D];
__device__ float g_qp2 [BS*LL*D];
__device__ float g_kp2 [BS*LL*D];
__device__ float g_vp2 [BS*LL*D];
__device__ float g_xmid[BS*LL*D];
__device__ float g_kvz [4*KVN];

// mega buffers: 4 msg sets, 4 hcat sets, 2 t sets (contiguous)
__device__ __align__(1024) __nv_bfloat16 g_mhi[4*ROWS*D],   g_mlo[4*ROWS*D];
__device__ __align__(1024) __nv_bfloat16 g_hhi[4*ROWS*2*D], g_hlo[4*ROWS*2*D];
__device__ __align__(1024) __nv_bfloat16 g_thi[2*ROWS*2*D], g_tlo[2*ROWS*2*D];

__device__ __align__(1024) __nv_bfloat16 g_wqh[D*D],     g_wql[D*D];
__device__ __align__(1024) __nv_bfloat16 g_wkvh[2*D*D],  g_wkvl[2*D*D];   // [Wk^T ; Wv^T]
__device__ __align__(1024) __nv_bfloat16 g_wmh[D*D],     g_wml[D*D];
__device__ __align__(1024) __nv_bfloat16 g_w1h[2*D*2*D], g_w1l[2*D*2*D];
__device__ __align__(1024) __nv_bfloat16 g_w2h[D*2*D],   g_w2l[D*2*D];

// ---------------- helpers ----------------
__device__ __forceinline__ float phi(float x) { return x > 0.f ? x + 1.f : __expf(x); }
__device__ __forceinline__ uint32_t smem_u32(const void* p) {
    uint32_t a;
    asm("{ .reg .u64 t; cvta.to.shared.u64 t, %1; cvt.u32.u64 %0, t; }" : "=r"(a) : "l"(p));
    return a;
}
__device__ __forceinline__ void split_store(__nv_bfloat16* hi, __nv_bfloat16* lo,
                                            size_t idx, float v) {
    __nv_bfloat16 h = __float2bfloat16(v);
    hi[idx] = h;
    lo[idx] = __float2bfloat16(v - __bfloat162float(h));
}
__device__ __forceinline__ int off21(int l, int c) {
    int F = l * 256 + c;
    int h0 = F / 153600;
    int rem = F - h0 * 153600;
    int l0 = rem >> 5;
    return l0 * 256 + h0 * 32 + (rem & 31);
}

#if HAS_TCGEN05
__device__ __forceinline__ void mbar_init(uint32_t a, uint32_t cnt) {
    asm volatile("mbarrier.init.shared.b64 [%0], %1;" :: "r"(a), "r"(cnt) : "memory");
}
__device__ __forceinline__ void mbar_wait(uint32_t a, uint32_t parity) {
    asm volatile(
        "{\n\t.reg .pred P;\n"
        "W_%=:\n\t"
        "mbarrier.try_wait.parity.acquire.cta.shared::cta.b64 P, [%0], %1, 0x989680;\n\t"
        "@!P bra W_%=;\n\t}"
        :: "r"(a), "r"(parity) : "memory");
}
__device__ __forceinline__ void mbar_expect_tx(uint32_t a, uint32_t bytes) {
    asm volatile("mbarrier.arrive.expect_tx.shared.b64 _, [%0], %1;"
                 :: "r"(a), "r"(bytes) : "memory");
}
__device__ __forceinline__ void tma2d(uint32_t smem, const CUtensorMap* map,
                                      int x, int y, uint32_t mbar) {
    asm volatile(
        "cp.async.bulk.tensor.2d.shared::cta.global.tile.mbarrier::complete_tx::bytes "
        "[%0], [%1, {%2, %3}], [%4];"
        :: "r"(smem), "l"(map), "r"(x), "r"(y), "r"(mbar) : "memory");
}
// SW64 descriptor: layout=4, version=1 (Blackwell), SBO=32, LBO=1
__device__ __forceinline__ uint64_t make_desc64(uint32_t addr) {
    const uint64_t base = (uint64_t(4) << 61) | (uint64_t(1) << 46)
                        | (uint64_t(32) << 32) | (uint64_t(1) << 16);
    return base | ((uint64_t)(addr >> 4) & 0x3FFF);
}
__device__ __forceinline__ void mma_f16_ss(uint32_t d, uint64_t a, uint64_t b,
                                           uint32_t idesc, uint32_t en) {
    asm volatile(
        "{\n\t.reg .pred p;\n\tsetp.ne.u32 p, %5, 0;\n\t"
        "tcgen05.mma.cta_group::1.kind::f16 [%0], %1, %2, %3, {%4, %4, %4, %4}, p;\n\t}"
        :: "r"(d), "l"(a), "l"(b), "r"(idesc), "r"(0u), "r"(en) : "memory");
}
__device__ __forceinline__ void tc_commit(uint32_t mbar) {
    asm volatile(
        "tcgen05.commit.cta_group::1.mbarrier::arrive::one.shared::cluster.b64 [%0];"
        :: "r"(mbar) : "memory");
}
__device__ __forceinline__ void ldtm32(uint32_t* r, uint32_t addr) {
    asm volatile(
        "tcgen05.ld.sync.aligned.32x32b.x32.b32 "
        "{%0, %1, %2, %3, %4, %5, %6, %7, "
        " %8, %9, %10, %11, %12, %13, %14, %15, "
        " %16, %17, %18, %19, %20, %21, %22, %23, "
        " %24, %25, %26, %27, %28, %29, %30, %31}, [%32];"
        : "=r"(r[0]),  "=r"(r[1]),  "=r"(r[2]),  "=r"(r[3]),
          "=r"(r[4]),  "=r"(r[5]),  "=r"(r[6]),  "=r"(r[7]),
          "=r"(r[8]),  "=r"(r[9]),  "=r"(r[10]), "=r"(r[11]),
          "=r"(r[12]), "=r"(r[13]), "=r"(r[14]), "=r"(r[15]),
          "=r"(r[16]), "=r"(r[17]), "=r"(r[18]), "=r"(r[19]),
          "=r"(r[20]), "=r"(r[21]), "=r"(r[22]), "=r"(r[23]),
          "=r"(r[24]), "=r"(r[25]), "=r"(r[26]), "=r"(r[27]),
          "=r"(r[28]), "=r"(r[29]), "=r"(r[30]), "=r"(r[31])
        : "r"(addr));
    asm volatile("tcgen05.wait::ld.sync.aligned;" ::: "memory");
}
#endif

// ---------------- convert kernels ----------------
__global__ void __launch_bounds__(256) aconv(const float4* __restrict__ a,
                                             __nv_bfloat162* __restrict__ hi,
                                             __nv_bfloat162* __restrict__ lo, int n4) {
    int i = blockIdx.x * 256 + threadIdx.x;
    if (i >= n4) return;
    float4 v = a[i];
    __nv_bfloat16 h0 = __float2bfloat16(v.x), h1 = __float2bfloat16(v.y);
    __nv_bfloat16 h2 = __float2bfloat16(v.z), h3 = __float2bfloat16(v.w);
    hi[2*i]   = __halves2bfloat162(h0, h1);
    hi[2*i+1] = __halves2bfloat162(h2, h3);
    lo[2*i]   = __halves2bfloat162(__float2bfloat16(v.x - __bfloat162float(h0)),
                                   __float2bfloat16(v.y - __bfloat162float(h1)));
    lo[2*i+1] = __halves2bfloat162(__float2bfloat16(v.z - __bfloat162float(h2)),
                                   __float2bfloat16(v.w - __bfloat162float(h3)));
}

__global__ void __launch_bounds__(256) wconv_all(
        const float* __restrict__ Wq, const float* __restrict__ Wk,
        const float* __restrict__ Wv, const float* __restrict__ Wm,
        const float* __restrict__ W1, const float* __restrict__ W2) {
    int i = blockIdx.x * 256 + threadIdx.x;
    if (i >= 655360) return;
    const float* W; __nv_bfloat16 *hi, *lo; int K, N, li = i;
    if (li < 65536)                { W = Wq; hi = g_wqh;          lo = g_wql;          K = 256; N = 256; }
    else if ((li -= 65536) < 65536){ W = Wk; hi = g_wkvh;         lo = g_wkvl;         K = 256; N = 256; }
    else if ((li -= 65536) < 65536){ W = Wv; hi = g_wkvh + 65536; lo = g_wkvl + 65536; K = 256; N = 256; }
    else if ((li -= 65536) < 65536){ W = Wm; hi = g_wmh;          lo = g_wml;          K = 256; N = 256; }
    else if ((li -= 65536) < 262144){ W = W1; hi = g_w1h;         lo = g_w1l;          K = 512; N = 512; }
    else { li -= 262144;             W = W2; hi = g_w2h;          lo = g_w2l;          K = 512; N = 256; }
    int n = li / K, k = li % K;
    float v = W[(size_t)k * N + n];
    __nv_bfloat16 h = __float2bfloat16(v);
    hi[li] = h;
    lo[li] = __float2bfloat16(v - __bfloat162float(h));
}

// xb -> copy to dst + hcat base halves of TWO consecutive sets (pitch 512)
__global__ void __launch_bounds__(256) prep_base2(const float4* __restrict__ xb,
                                                  float4* __restrict__ dst,
                                                  __nv_bfloat16* __restrict__ hhiA,
                                                  __nv_bfloat16* __restrict__ hloA,
                                                  __nv_bfloat16* __restrict__ hhiB,
                                                  __nv_bfloat16* __restrict__ hloB) {
    int i = blockIdx.x * 256 + threadIdx.x;
    if (i >= ROWS * 64) return;
    float4 v = xb[i];
    dst[i] = v;
    int row = i >> 6, j = i & 63;
    size_t o = (size_t)row * 512 + j * 4;
    float vv[4] = {v.x, v.y, v.z, v.w};
    #pragma unroll
    for (int e = 0; e < 4; e++) {
        __nv_bfloat16 h = __float2bfloat16(vv[e]);
        __nv_bfloat16 l = __float2bfloat16(vv[e] - __bfloat162float(h));
        hhiA[o + e] = h; hloA[o + e] = l;
        hhiB[o + e] = h; hloB[o + e] = l;
    }
}

// ---------------- tcgen05 GEMM, BK=32/SW64, 2 CTAs/SM, smem-staged epilogue ----------------
// EPI 0: fp32 -> Cf (or Cf2 when bn >= nsplit) ; EPI 1: relu -> bf16 hi/lo ;
// EPI 2: LN -> bf16 hi/lo at coff ; EPI 3: atomicAdd(Cf, 0.5*LN) with row mod rowmod
template<int EPI>
__global__ void __launch_bounds__(256, 2) tc_gemm(
        const __grid_constant__ CUtensorMap mAh, const __grid_constant__ CUtensorMap mAl,
        const __grid_constant__ CUtensorMap mBh, const __grid_constant__ CUtensorMap mBl,
        const __nv_bfloat16* __restrict__ Ahi, const __nv_bfloat16* __restrict__ Alo,
        const __nv_bfloat16* __restrict__ Bhi, const __nv_bfloat16* __restrict__ Blo,
        float* __restrict__ Cf, float* __restrict__ Cf2,
        __nv_bfloat16* __restrict__ Chi, __nv_bfloat16* __restrict__ Clo,
        const float* __restrict__ Gw, const float* __restrict__ Bw,
        int K, int ldc, int coff, int rowmod, int nsplit) {
#if HAS_TCGEN05
    extern __shared__ char dsm_raw[];
    char* sbase = (char*)(((uintptr_t)dsm_raw + 1023) & ~(uintptr_t)1023);
    __shared__ uint32_t s_tmem;
    __shared__ __align__(8) unsigned long long s_mbar[4];
    const uint32_t mb = smem_u32(s_mbar);
    const int t = threadIdx.x, wid = t >> 5, lane = t & 31;

    if (wid == 0) {
        asm volatile("tcgen05.alloc.cta_group::1.sync.aligned.shared::cta.b32 [%0], %1;"
                     :: "r"(smem_u32(&s_tmem)), "r"(256u) : "memory");
        asm volatile("tcgen05.relinquish_alloc_permit.cta_group::1.sync.aligned;");
    }
    if (t == 0) {
        mbar_init(mb, 1); mbar_init(mb + 8, 1);
        mbar_init(mb + 16, 1); mbar_init(mb + 24, 1);
    }
    __syncthreads();
    const uint32_t tmem = s_tmem;

    const int bm = blockIdx.y * BM, bn = blockIdx.x * BN;
    const int NC = K >> 5;
    const uint32_t idesc = (1u << 4) | (1u << 7) | (1u << 10)
                         | ((BN / 8) << 17) | ((BM / 16) << 24);
    const uint32_t sb32 = smem_u32(sbase);

    if (t == 0) {
        mbar_expect_tx(mb, STAGE_BYTES);
        tma2d(sb32 + A_HI, &mAh, 0, bm, mb);
        tma2d(sb32 + A_LO, &mAl, 0, bm, mb);
        tma2d(sb32 + B_HI, &mBh, 0, bn, mb);
        tma2d(sb32 + B_LO, &mBl, 0, bn, mb);
        if (NC > 1) {
            uint32_t st = sb32 + STAGE_BYTES;
            mbar_expect_tx(mb + 8, STAGE_BYTES);
            tma2d(st + A_HI, &mAh, BK, bm, mb + 8);
            tma2d(st + A_LO, &mAl, BK, bm, mb + 8);
            tma2d(st + B_HI, &mBh, BK, bn, mb + 8);
            tma2d(st + B_LO, &mBl, BK, bn, mb + 8);
        }
        int fph[2] = {0, 0}, mph[2] = {0, 0}, pend[2] = {0, 0};
        for (int c = 0; c < NC; c++) {
            const int s = c & 1;
            mbar_wait(mb + s * 8, fph[s]); fph[s] ^= 1;
            uint32_t st = sb32 + s * STAGE_BYTES;
            uint64_t dAh = make_desc64(st + A_HI), dAl = make_desc64(st + A_LO);
            uint64_t dBh = make_desc64(st + B_HI), dBl = make_desc64(st + B_LO);
            #pragma unroll
            for (int kk2 = 0; kk2 < 2; kk2++) {
                mma_f16_ss(tmem, dAh + kk2 * 2, dBh + kk2 * 2, idesc, (c > 0) || (kk2 > 0));
                mma_f16_ss(tmem, dAh + kk2 * 2, dBl + kk2 * 2, idesc, 1u);
                mma_f16_ss(tmem, dAl + kk2 * 2, dBh + kk2 * 2, idesc, 1u);
            }
            tc_commit(mb + 16 + s * 8);
            pend[s] = 1;
            if (c + 2 < NC) {
                mbar_wait(mb + 16 + s * 8, mph[s]); mph[s] ^= 1; pend[s] = 0;
                int k0 = (c + 2) * BK;
                mbar_expect_tx(mb + s * 8, STAGE_BYTES);
                tma2d(st + A_HI, &mAh, k0, bm, mb + s * 8);
                tma2d(st + A_LO, &mAl, k0, bm, mb + s * 8);
                tma2d(st + B_HI, &mBh, k0, bn, mb + s * 8);
                tma2d(st + B_LO, &mBl, k0, bn, mb + s * 8);
            }
        }
        if (pend[0]) mbar_wait(mb + 16, mph[0]);
        if (pend[1]) mbar_wait(mb + 24, mph[1]);
    }
    __syncthreads();
    asm volatile("tcgen05.fence::after_thread_sync;" ::: "memory");

    // smem-staged, coalesced epilogue
    float* Co = Cf;
    int bnc = bn;
    if (EPI == 0 && nsplit && bn >= nsplit) { Co = Cf2; bnc = bn - nsplit; }

    float (*tile)[33] = (float(*)[33])sbase;
    float mean = 0.f, rstd = 0.f;
    if (EPI >= 2 && wid < 4) {
        float s = 0.f, s2 = 0.f;
        #pragma unroll
        for (int ch = 0; ch < 8; ch++) {
            uint32_t r[32];
            ldtm32(r, tmem + ch * 32);
            #pragma unroll
            for (int j = 0; j < 32; j++) {
                float v = __uint_as_float(r[j]);
                s += v; s2 += v * v;
            }
        }
        mean = s * (1.f / 256.f);
        float var = fmaf(-mean, mean, s2 * (1.f / 256.f));
        rstd = rsqrtf(var + 1e-5f);
    }
    #pragma unroll
    for (int ch = 0; ch < 8; ch++) {
        if (wid < 4) {
            uint32_t r[32];
            ldtm32(r, tmem + ch * 32);
            int rloc = wid * 32 + lane;
            #pragma unroll
            for (int j = 0; j < 32; j++) {
                float v = __uint_as_float(r[j]);
                if (EPI == 1) v = fmaxf(v, 0.f);
                if (EPI >= 2) {
                    int col = ch * 32 + j;
                    v = (v - mean) * rstd * Gw[col] + Bw[col];
                    if (EPI == 3) v *= 0.5f;
                }
                tile[rloc][j] = v;
            }
        }
        __syncthreads();
        #pragma unroll
        for (int i = 0; i < 16; i++) {
            int idx = i * 256 + t;
            int rr = idx >> 5, cc = idx & 31;
            float v = tile[rr][cc];
            int orow = bm + rr;
            if (EPI == 3 && orow >= rowmod) orow -= rowmod;
            size_t ro = (size_t)orow * ldc + bnc + coff + ch * 32 + cc;
            if (EPI == 0)       Co[ro] = v;
            else if (EPI == 3)  atomicAdd(Cf + ro, v);
            else                split_store(Chi, Clo, ro, v);
        }
        __syncthreads();
    }
    if (wid == 0)
        asm volatile("tcgen05.dealloc.cta_group::1.sync.aligned.b32 %0, %1;"
                     :: "r"(tmem), "r"(256u));
#else
    // compile-only fallback (never runs on GB300)
    const int bm = blockIdx.y * BM, bn = blockIdx.x * BN;
    const int t = threadIdx.x;
    if (t < BM) {
        int row = bm + t;
        float vals[BN];
        for (int c = 0; c < BN; c++) {
            const __nv_bfloat16* ah = Ahi + (size_t)row * K;
            const __nv_bfloat16* al = Alo + (size_t)row * K;
            const __nv_bfloat16* bh = Bhi + (size_t)(bn + c) * K;
            const __nv_bfloat16* bl = Blo + (size_t)(bn + c) * K;
            float acc = 0.f;
            for (int kk = 0; kk < K; kk++)
                acc += (__bfloat162float(ah[kk]) + __bfloat162float(al[kk])) *
                       (__bfloat162float(bh[kk]) + __bfloat162float(bl[kk]));
            vals[c] = acc;
        }
        float mean = 0.f, rstd = 1.f;
        if (EPI >= 2) {
            float s = 0.f, s2 = 0.f;
            for (int c = 0; c < BN; c++) { s += vals[c]; s2 += vals[c] * vals[c]; }
            mean = s / BN;
            rstd = rsqrtf(s2 / BN - mean * mean + 1e-5f);
        }
        float* Co = Cf;
        int bnc = bn;
        if (EPI == 0 && nsplit && bn >= nsplit) { Co = Cf2; bnc = bn - nsplit; }
        for (int c = 0; c < BN; c++) {
            float v = vals[c];
            if (EPI == 1) v = fmaxf(v, 0.f);
            if (EPI >= 2) { v = (v - mean) * rstd * Gw[c] + Bw[c]; if (EPI == 3) v *= 0.5f; }
            int orow = row;
            if (EPI == 3 && orow >= rowmod) orow -= rowmod;
            size_t ro = (size_t)orow * ldc + bnc + coff + c;
            if (EPI == 0)      Co[ro] = v;
            else if (EPI == 3) atomicAdd(Cf + ro, v);
            else               split_store(Chi, Clo, ro, v);
        }
    }
#endif
}

// ---------------- coalesced permutes ----------------
__global__ void __launch_bounds__(256) perm13(const float* q, const float* k, const float* v,
                                              float* qd, float* kd, float* vd) {
    __shared__ float s[8][256];
    const float* S = blockIdx.z == 0 ? q : (blockIdx.z == 1 ? k : v);
    float* Dd = blockIdx.z == 0 ? qd : (blockIdx.z == 1 ? kd : vd);
    size_t rowbase = (size_t)blockIdx.x * 8;
    int t = threadIdx.x;
    #pragma unroll
    for (int i = 0; i < 8; i++) s[i][t] = S[(rowbase + i) * 256 + t];
    __syncthreads();
    int c0 = (t & 7) * 32 + (t >> 3);
    #pragma unroll
    for (int i = 0; i < 8; i++) Dd[(rowbase + i) * 256 + t] = s[i][c0];
}

__global__ void __launch_bounds__(256) perm32(const float* q, const float* k, const float* v,
                                              float* qd, float* kd, float* vd) {
    __shared__ float sm[32][33];
    const float* S = blockIdx.z == 0 ? q : (blockIdx.z == 1 ? k : v);
    float* Dd = blockIdx.z == 0 ? qd : (blockIdx.z == 1 ? kd : vd);
    int b = blockIdx.y;
    int l0b = blockIdx.x * 32;
    size_t bo = (size_t)b * BSTRIDE;
    int wr = threadIdx.x >> 5, lane = threadIdx.x & 31;
    for (int h0 = 0; h0 < H; h0++) {
        #pragma unroll
        for (int it = 0; it < 4; it++) {
            int row = wr + it * 8;
            sm[row][lane] = S[bo + (size_t)(l0b + row) * 256 + h0 * 32 + lane];
        }
        __syncthreads();
        #pragma unroll
        for (int it = 0; it < 4; it++) {
            int d0 = wr + it * 8;
            Dd[bo + (size_t)d0 * 38400 + h0 * 4800 + l0b + lane] = sm[lane][d0];
        }
        __syncthreads();
    }
}

// ---------------- KV reduce for TWO sets (blockIdx.z in {0,1}) ----------------
#define KVSPLIT 10
#define KVCHUNK (LL/KVSPLIT)
__global__ void __launch_bounds__(256) kv_mega2(
        const float* k0, const float* v0, const float* k1, const float* v1,
        float* __restrict__ kvzg, int m21mask) {
    int si = blockIdx.z;
    const float* kk = si == 0 ? k0 : k1;
    const float* vv = si == 0 ? v0 : v1;
    bool m21 = (m21mask >> si) & 1;
    float* kvz = kvzg + (size_t)si * KVN;
    int b = blockIdx.x >> 3, h = blockIdx.x & 7;
    int sbeg = blockIdx.y * KVCHUNK;
    const float* kb = kk + (size_t)b * BSTRIDE;
    const float* vb = vv + (size_t)b * BSTRIDE;
    __shared__ float ks[8][32], vs[8][32];
    int t = threadIdx.x;
    int r = t >> 5, c = t & 31;
    float acc[4] = {0.f, 0.f, 0.f, 0.f};
    float ksacc = 0.f;
    for (int s0 = sbeg; s0 < sbeg + KVCHUNK; s0 += 8) {
        int off = m21 ? off21(s0 + r, h * DH + c) : (s0 + r) * 256 + h * DH + c;
        ks[r][c] = phi(kb[off]);
        vs[r][c] = vb[off];
        __syncthreads();
        #pragma unroll
        for (int row = 0; row < 8; row++) {
            float ve = vs[row][c];
            #pragma unroll
            for (int jj = 0; jj < 4; jj++)
                acc[jj] += ks[row][r + jj * 8] * ve;
        }
        if (t < 32) {
            #pragma unroll
            for (int row = 0; row < 8; row++) ksacc += ks[row][t];
        }
        __syncthreads();
    }
    float* kvout = kvz + (size_t)(b * H + h) * DH * DH;
    #pragma unroll
    for (int jj = 0; jj < 4; jj++)
        atomicAdd(&kvout[(r + jj * 8) * DH + c], acc[jj]);
    if (t < 32) atomicAdd(&kvz[BS*H*DH*DH + (b * H + h) * DH + t], ksacc);
}

// ---------------- attention apply for TWO sets (blockIdx.z in {0,1}) ----------------
__global__ void __launch_bounds__(256) attn_mega2(
        const float* q0, const float* q1,
        const float* __restrict__ kvzg,
        __nv_bfloat16* __restrict__ mhig, __nv_bfloat16* __restrict__ mlog,
        int m21mask) {
    extern __shared__ float as_[];
    float* sKV = as_;
    float* sKs = sKV + H * DH * DH;
    float (*sQ)[256] = (float(*)[256])(sKs + H * DH);
    float* sZ = (float*)(sQ + ATOK);
    int si = blockIdx.z;
    const float* qsel = si == 0 ? q0 : q1;
    bool m21 = (m21mask >> si) & 1;
    const float* kvz = kvzg + (size_t)si * KVN;
    __nv_bfloat16* mhi = mhig + (size_t)si * ROWS * D;
    __nv_bfloat16* mlo = mlog + (size_t)si * ROWS * D;
    int b  = blockIdx.y;
    int l0 = blockIdx.x * ATOK;
    int t = threadIdx.x;
    const float* kvb = kvz + (size_t)b * H * DH * DH;
    #pragma unroll
    for (int i = t; i < H * DH * DH; i += 256) sKV[i] = kvb[i];
    if (t < H * DH) sKs[t] = kvz[BS*H*DH*DH + b * H * DH + t];
    const float* qb = qsel + (size_t)b * BSTRIDE;
    #pragma unroll
    for (int i = 0; i < ATOK; i++) {
        int off = m21 ? off21(l0 + i, t) : (l0 + i) * 256 + t;
        sQ[i][t] = phi(qb[off]);
    }
    __syncthreads();
    {
        int tok = t >> 3, h = t & 7;
        float z = 0.f;
        #pragma unroll
        for (int d = 0; d < DH; d++) z += sQ[tok][h * DH + d] * sKs[h * DH + d];
        sZ[tok * H + h] = 1.f / (z + 1e-6f);
    }
    __syncthreads();
    int c = t, h = c >> 5, e = c & 31;
    float kvreg[DH];
    #pragma unroll
    for (int d = 0; d < DH; d++) kvreg[d] = sKV[(h * DH + d) * DH + e];
    size_t base = (size_t)b * BSTRIDE + (size_t)l0 * D;
    #pragma unroll 4
    for (int jj = 0; jj < ATOK; jj++) {
        float dot = 0.f;
        #pragma unroll
        for (int d = 0; d < DH; d++)
            dot += sQ[jj][h * DH + d] * kvreg[d];
        split_store(mhi, mlo, base + (size_t)jj * D + c, dot * sZ[jj * H + h]);
    }
}

// ---------------- host orchestration ----------------
typedef CUresult (*EncFn)(CUtensorMap*, CUtensorMapDataType, cuuint32_t, void*,
        const cuuint64_t*, const cuuint64_t*, const cuuint32_t*, const cuuint32_t*,
        CUtensorMapInterleave, CUtensorMapSwizzle, CUtensorMapL2promotion,
        CUtensorMapFloatOOBfill);

extern "C" void kernel_launch(void* const* d_in, const int* in_sizes, int n_in,
                              void* d_out, int out_size) {
    (void)in_sizes; (void)n_in; (void)out_size;
    const float* x   = (const float*)d_in[0];
    const float* src = (const float*)d_in[1];
    const float* Wq  = (const float*)d_in[2];
    const float* Wk  = (const float*)d_in[3];
    const float* Wv  = (const float*)d_in[4];
    const float* Wm  = (const float*)d_in[5];
    const float* W1  = (const float*)d_in[6];
    const float* W2  = (const float*)d_in[7];
    const float* g1  = (const float*)d_in[8];
    const float* b1  = (const float*)d_in[9];
    const float* g2  = (const float*)d_in[10];
    const float* b2  = (const float*)d_in[11];
    float* out = (float*)d_out;

    float *q, *k, *v, *qp1, *kp1, *vp1, *qp2, *kp2, *vp2, *xmid, *kvz;
    cudaGetSymbolAddress((void**)&q,    g_q);
    cudaGetSymbolAddress((void**)&k,    g_k);
    cudaGetSymbolAddress((void**)&v,    g_v);
    cudaGetSymbolAddress((void**)&qp1,  g_qp1);
    cudaGetSymbolAddress((void**)&kp1,  g_kp1);
    cudaGetSymbolAddress((void**)&vp1,  g_vp1);
    cudaGetSymbolAddress((void**)&qp2,  g_qp2);
    cudaGetSymbolAddress((void**)&kp2,  g_kp2);
    cudaGetSymbolAddress((void**)&vp2,  g_vp2);
    cudaGetSymbolAddress((void**)&xmid, g_xmid);
    cudaGetSymbolAddress((void**)&kvz,  g_kvz);

    __nv_bfloat16 *mhi, *mlo, *hhi, *hlo, *thi, *tlo;
    cudaGetSymbolAddress((void**)&mhi, g_mhi); cudaGetSymbolAddress((void**)&mlo, g_mlo);
    cudaGetSymbolAddress((void**)&hhi, g_hhi); cudaGetSymbolAddress((void**)&hlo, g_hlo);
    cudaGetSymbolAddress((void**)&thi, g_thi); cudaGetSymbolAddress((void**)&tlo, g_tlo);

    __nv_bfloat16 *wqh, *wql, *wkvh, *wkvl, *wmh, *wml, *w1h, *w1l, *w2h, *w2l;
    cudaGetSymbolAddress((void**)&wqh, g_wqh);   cudaGetSymbolAddress((void**)&wql, g_wql);
    cudaGetSymbolAddress((void**)&wkvh, g_wkvh); cudaGetSymbolAddress((void**)&wkvl, g_wkvl);
    cudaGetSymbolAddress((void**)&wmh, g_wmh);   cudaGetSymbolAddress((void**)&wml, g_wml);
    cudaGetSymbolAddress((void**)&w1h, g_w1h);   cudaGetSymbolAddress((void**)&w1l, g_w1l);
    cudaGetSymbolAddress((void**)&w2h, g_w2h);   cudaGetSymbolAddress((void**)&w2l, g_w2l);

    EncFn enc = nullptr;
    {
        void* fp = nullptr;
#if CUDART_VERSION >= 12050
        cudaDriverEntryPointQueryResult qr;
        cudaGetDriverEntryPoint("cuTensorMapEncodeTiled", &fp, cudaEnableDefault, &qr);
#else
        cudaGetDriverEntryPoint("cuTensorMapEncodeTiled", &fp, cudaEnableDefault);
#endif
        enc = (EncFn)fp;
    }
    auto mk = [&](void* ptr, uint64_t k_elems, uint64_t rows, uint32_t boxrows) {
        CUtensorMap m{};
        cuuint64_t dims[2] = {k_elems, rows};
        cuuint64_t strides[1] = {k_elems * 2};
        cuuint32_t box[2] = {32, boxrows};
        cuuint32_t es[2] = {1, 1};
        enc(&m, CU_TENSOR_MAP_DATA_TYPE_BFLOAT16, 2, ptr, dims, strides, box, es,
            CU_TENSOR_MAP_INTERLEAVE_NONE, CU_TENSOR_MAP_SWIZZLE_64B,
            CU_TENSOR_MAP_L2_PROMOTION_L2_128B, CU_TENSOR_MAP_FLOAT_OOB_FILL_NONE);
        return m;
    };
    CUtensorMap tm_mA   = mk(mhi, 256, ROWS, 128);
    CUtensorMap tm_mAl  = mk(mlo, 256, ROWS, 128);
    CUtensorMap tm_mB   = mk(mhi + (size_t)ROWS*D, 256, ROWS, 128);
    CUtensorMap tm_mBl  = mk(mlo + (size_t)ROWS*D, 256, ROWS, 128);
    CUtensorMap tm_m01  = mk(mhi, 256, 2*(uint64_t)ROWS, 128);
    CUtensorMap tm_m01l = mk(mlo, 256, 2*(uint64_t)ROWS, 128);
    CUtensorMap tm_m23  = mk(mhi + (size_t)2*ROWS*D, 256, 2*(uint64_t)ROWS, 128);
    CUtensorMap tm_m23l = mk(mlo + (size_t)2*ROWS*D, 256, 2*(uint64_t)ROWS, 128);
    CUtensorMap tm_h1   = mk(hhi, 512, 2*(uint64_t)ROWS, 128);
    CUtensorMap tm_h1l  = mk(hlo, 512, 2*(uint64_t)ROWS, 128);
    CUtensorMap tm_h2   = mk(hhi + (size_t)2*ROWS*512, 512, 2*(uint64_t)ROWS, 128);
    CUtensorMap tm_h2l  = mk(hlo + (size_t)2*ROWS*512, 512, 2*(uint64_t)ROWS, 128);
    CUtensorMap tm_t    = mk(thi, 512, 2*(uint64_t)ROWS, 128);
    CUtensorMap tm_tl   = mk(tlo, 512, 2*(uint64_t)ROWS, 128);
    CUtensorMap tm_wqh = mk(wqh, 256, 256, 256), tm_wql = mk(wql, 256, 256, 256);
    CUtensorMap tm_wkv = mk(wkvh, 256, 512, 256), tm_wkvl = mk(wkvl, 256, 512, 256);
    CUtensorMap tm_wmh = mk(wmh, 256, 256, 256), tm_wml = mk(wml, 256, 256, 256);
    CUtensorMap tm_w1h = mk(w1h, 512, 512, 256), tm_w1l = mk(w1l, 512, 512, 256);
    CUtensorMap tm_w2h = mk(w2h, 512, 256, 256), tm_w2l = mk(w2l, 512, 256, 256);

    cudaFuncSetAttribute(tc_gemm<0>, cudaFuncAttributeMaxDynamicSharedMemorySize, SMEM_DYN);
    cudaFuncSetAttribute(tc_gemm<1>, cudaFuncAttributeMaxDynamicSharedMemorySize, SMEM_DYN);
    cudaFuncSetAttribute(tc_gemm<2>, cudaFuncAttributeMaxDynamicSharedMemorySize, SMEM_DYN);
    cudaFuncSetAttribute(tc_gemm<3>, cudaFuncAttributeMaxDynamicSharedMemorySize, SMEM_DYN);
    const int ATTN_SMEM = (H*DH*DH + H*DH + ATOK*256 + ATOK*H) * 4;
    cudaFuncSetAttribute(attn_mega2, cudaFuncAttributeMaxDynamicSharedMemorySize, ATTN_SMEM);

    static cudaStream_t s1 = nullptr, s2 = nullptr;
    static cudaEvent_t ev[8];
    if (!s1) {
        cudaStreamCreateWithFlags(&s1, cudaStreamNonBlocking);
        cudaStreamCreateWithFlags(&s2, cudaStreamNonBlocking);
        for (int i = 0; i < 8; i++)
            cudaEventCreateWithFlags(&ev[i], cudaEventDisableTiming);
    }
    cudaEvent_t evW = ev[0], evQ = ev[1], evKV = ev[2], evPrep1 = ev[3],
                evX1 = ev[4], evWm23 = ev[5];

    dim3 thr(256);

    // root
    wconv_all<<<2560, thr>>>(Wq, Wk, Wv, Wm, W1, W2);
    cudaEventRecord(evW, 0);
    prep_base2<<<ROWS*64/256, thr>>>((const float4*)x, (float4*)xmid,
            hhi, hlo, hhi + (size_t)ROWS*512, hlo + (size_t)ROWS*512);
    cudaEventRecord(evPrep1, 0);
    cudaStreamWaitEvent(s1, evW, 0);
    cudaStreamWaitEvent(s2, evW, 0);

    // s1: aconv(x into m set0) + Wq
    aconv<<<ROWS*D/4/256, thr, 0, s1>>>((const float4*)x,
            (__nv_bfloat162*)mhi, (__nv_bfloat162*)mlo, ROWS*D/4);
    tc_gemm<0><<<dim3(1, ROWS/BM), thr, SMEM_DYN, s1>>>(tm_mA, tm_mAl, tm_wqh, tm_wql,
            mhi, mlo, wqh, wql, q, nullptr, nullptr, nullptr, nullptr, nullptr,
            D, D, 0, 0, 0);
    cudaEventRecord(evQ, s1);

    // s2: aconv(src into m set1) + merged Wk|Wv
    aconv<<<ROWS*D/4/256, thr, 0, s2>>>((const float4*)src,
            (__nv_bfloat162*)(mhi + (size_t)ROWS*D), (__nv_bfloat162*)(mlo + (size_t)ROWS*D),
            ROWS*D/4);
    tc_gemm<0><<<dim3(2, ROWS/BM), thr, SMEM_DYN, s2>>>(tm_mB, tm_mBl, tm_wkv, tm_wkvl,
            mhi + (size_t)ROWS*D, mlo + (size_t)ROWS*D, wkvh, wkvl,
            k, v, nullptr, nullptr, nullptr, nullptr, D, D, 0, 0, 256);
    cudaEventRecord(evKV, s2);

    // ---- s1 chain: sets 0,1 (mode0 + perm13) then phase-1 MLP ----
    cudaStreamWaitEvent(s1, evKV, 0);
    perm13<<<dim3(ROWS/8, 1, 3), thr, 0, s1>>>(q, k, v, qp1, kp1, vp1);
    cudaMemsetAsync(kvz, 0, (size_t)2 * KVN * sizeof(float), s1);
    kv_mega2<<<dim3(BS*H, KVSPLIT, 2), thr, 0, s1>>>(k, v, kp1, vp1, kvz, 0x0);
    attn_mega2<<<dim3(LL/ATOK, BS, 2), thr, ATTN_SMEM, s1>>>(q, qp1, kvz, mhi, mlo, 0x0);
    tc_gemm<2><<<dim3(1, 2*ROWS/BM), thr, SMEM_DYN, s1>>>(tm_m01, tm_m01l, tm_wmh, tm_wml,
            mhi, mlo, wmh, wml, nullptr, nullptr, hhi, hlo, g1, b1, D, 2*D, D, 0, 0);
    cudaStreamWaitEvent(s1, evPrep1, 0);
    tc_gemm<1><<<dim3(2, 2*ROWS/BM), thr, SMEM_DYN, s1>>>(tm_h1, tm_h1l, tm_w1h, tm_w1l,
            hhi, hlo, w1h, w1l, nullptr, nullptr, thi, tlo, nullptr, nullptr,
            2*D, 2*D, 0, 0, 0);
    tc_gemm<3><<<dim3(1, 2*ROWS/BM), thr, SMEM_DYN, s1>>>(tm_t, tm_tl, tm_w2h, tm_w2l,
            thi, tlo, w2h, w2l, xmid, nullptr, nullptr, nullptr, g2, b2,
            2*D, D, 0, ROWS, 0);
    cudaEventRecord(evX1, s1);

    // ---- s2 chain: sets 2,3 (mode21 + perm32), attn + Wm only ----
    cudaStreamWaitEvent(s2, evQ, 0);
    perm32<<<dim3(150, BS, 3), thr, 0, s2>>>(q, k, v, qp2, kp2, vp2);
    cudaMemsetAsync(kvz + (size_t)2 * KVN, 0, (size_t)2 * KVN * sizeof(float), s2);
    kv_mega2<<<dim3(BS*H, KVSPLIT, 2), thr, 0, s2>>>(k, v, kp2, vp2,
            kvz + (size_t)2 * KVN, 0x1);
    attn_mega2<<<dim3(LL/ATOK, BS, 2), thr, ATTN_SMEM, s2>>>(q, qp2,
            kvz + (size_t)2 * KVN, mhi + (size_t)2*ROWS*D, mlo + (size_t)2*ROWS*D, 0x1);
    tc_gemm<2><<<dim3(1, 2*ROWS/BM), thr, SMEM_DYN, s2>>>(tm_m23, tm_m23l, tm_wmh, tm_wml,
            mhi + (size_t)2*ROWS*D, mlo + (size_t)2*ROWS*D, wmh, wml,
            nullptr, nullptr, hhi + (size_t)2*ROWS*512, hlo + (size_t)2*ROWS*512,
            g1, b1, D, 2*D, D, 0, 0);
    cudaEventRecord(evWm23, s2);

    // ---- join: prep2 (out = xmid; base halves 2,3), then phase-2 MLP ----
    cudaStreamWaitEvent(0, evX1, 0);
    prep_base2<<<ROWS*64/256, thr>>>((const float4*)xmid, (float4*)out,
            hhi + (size_t)2*ROWS*512, hlo + (size_t)2*ROWS*512,
            hhi + (size_t)3*ROWS*512, hlo + (size_t)3*ROWS*512);
    cudaStreamWaitEvent(0, evWm23, 0);
    tc_gemm<1><<<dim3(2, 2*ROWS/BM), thr, SMEM_DYN>>>(tm_h2, tm_h2l, tm_w1h, tm_w1l,
            hhi + (size_t)2*ROWS*512, hlo + (size_t)2*ROWS*512, w1h, w1l,
            nullptr, nullptr, thi, tlo, nullptr, nullptr, 2*D, 2*D, 0, 0, 0);
    tc_gemm<3><<<dim3(1, 2*ROWS/BM), thr, SMEM_DYN>>>(tm_t, tm_tl, tm_w2h, tm_w2l,
            thi, tlo, w2h, w2l, out, nullptr, nullptr, nullptr, g2, b2,
            2*D, D, 0, ROWS, 0);
}

// round 16
// speedup vs baseline: 1.6768x; 1.0414x over previous
#include <cuda_runtime.h>
#include <cuda.h>
#include <cuda_bf16.h>
#include <math.h>
#include <stdint.h>

#if defined(__CUDA_ARCH__) && defined(__CUDA_ARCH_FEAT_SM103_ALL)
#define HAS_TCGEN05 1
#else
#define HAS_TCGEN05 0
#endif

#define BS 8
#define LL 4800
#define D 256
#define H 8
#define DH 32
#define ROWS (BS*LL)   // 38400
#define BSTRIDE (LL*D)

#define BM 128
#define BN 256
#define BK 32
// SW64 stage layout: Ahi 8K | Alo 8K | Bhi 16K | Blo 16K = 48K
#define A_HI 0
#define A_LO 8192
#define B_HI 16384
#define B_LO 32768
#define STAGE_BYTES 49152
#define SMEM_DYN (2*STAGE_BYTES + 1024)

#define ATOK 32
#define KVN (BS*H*DH*DH + BS*H*DH)

// ---------------- scratch (device globals) ----------------
__device__ float g_q   [BS*LL*D];
__device__ float g_k   [BS*LL*D];
__device__ float g_v   [BS*LL*D];
__device__ float g_qp1 [BS*LL*D];
__device__ float g_kp1 [BS*LL*D];
__device__ float g_vp1 [BS*LL*D];
__device__ float g_qp2 [BS*LL*D];
__device__ float g_kp2 [BS*LL*D];
__device__ float g_vp2 [BS*LL*D];
__device__ float g_xmid[BS*LL*D];
__device__ float g_kvz [4*KVN];

// mega buffers: 4 msg sets, 4 hcat sets, 2 t sets (contiguous)
__device__ __align__(1024) __nv_bfloat16 g_mhi[4*ROWS*D],   g_mlo[4*ROWS*D];
__device__ __align__(1024) __nv_bfloat16 g_hhi[4*ROWS*2*D], g_hlo[4*ROWS*2*D];
__device__ __align__(1024) __nv_bfloat16 g_thi[2*ROWS*2*D], g_tlo[2*ROWS*2*D];

__device__ __align__(1024) __nv_bfloat16 g_wqh[D*D],     g_wql[D*D];
__device__ __align__(1024) __nv_bfloat16 g_wkvh[2*D*D],  g_wkvl[2*D*D];   // [Wk^T ; Wv^T]
__device__ __align__(1024) __nv_bfloat16 g_wmh[D*D],     g_wml[D*D];
__device__ __align__(1024) __nv_bfloat16 g_w1h[2*D*2*D], g_w1l[2*D*2*D];
__device__ __align__(1024) __nv_bfloat16 g_w2h[D*2*D],   g_w2l[D*2*D];

// ---------------- helpers ----------------
__device__ __forceinline__ float phi(float x) { return x > 0.f ? x + 1.f : __expf(x); }
__device__ __forceinline__ uint32_t smem_u32(const void* p) {
    uint32_t a;
    asm("{ .reg .u64 t; cvta.to.shared.u64 t, %1; cvt.u32.u64 %0, t; }" : "=r"(a) : "l"(p));
    return a;
}
__device__ __forceinline__ void split_store(__nv_bfloat16* hi, __nv_bfloat16* lo,
                                            size_t idx, float v) {
    __nv_bfloat16 h = __float2bfloat16(v);
    hi[idx] = h;
    lo[idx] = __float2bfloat16(v - __bfloat162float(h));
}
__device__ __forceinline__ int off21(int l, int c) {
    int F = l * 256 + c;
    int h0 = F / 153600;
    int rem = F - h0 * 153600;
    int l0 = rem >> 5;
    return l0 * 256 + h0 * 32 + (rem & 31);
}

#if HAS_TCGEN05
__device__ __forceinline__ void mbar_init(uint32_t a, uint32_t cnt) {
    asm volatile("mbarrier.init.shared.b64 [%0], %1;" :: "r"(a), "r"(cnt) : "memory");
}
__device__ __forceinline__ void mbar_wait(uint32_t a, uint32_t parity) {
    asm volatile(
        "{\n\t.reg .pred P;\n"
        "W_%=:\n\t"
        "mbarrier.try_wait.parity.acquire.cta.shared::cta.b64 P, [%0], %1, 0x989680;\n\t"
        "@!P bra W_%=;\n\t}"
        :: "r"(a), "r"(parity) : "memory");
}
__device__ __forceinline__ void mbar_expect_tx(uint32_t a, uint32_t bytes) {
    asm volatile("mbarrier.arrive.expect_tx.shared.b64 _, [%0], %1;"
                 :: "r"(a), "r"(bytes) : "memory");
}
__device__ __forceinline__ void tma2d(uint32_t smem, const CUtensorMap* map,
                                      int x, int y, uint32_t mbar) {
    asm volatile(
        "cp.async.bulk.tensor.2d.shared::cta.global.tile.mbarrier::complete_tx::bytes "
        "[%0], [%1, {%2, %3}], [%4];"
        :: "r"(smem), "l"(map), "r"(x), "r"(y), "r"(mbar) : "memory");
}
// SW64 descriptor: layout=4, version=1 (Blackwell), SBO=32, LBO=1
__device__ __forceinline__ uint64_t make_desc64(uint32_t addr) {
    const uint64_t base = (uint64_t(4) << 61) | (uint64_t(1) << 46)
                        | (uint64_t(32) << 32) | (uint64_t(1) << 16);
    return base | ((uint64_t)(addr >> 4) & 0x3FFF);
}
__device__ __forceinline__ void mma_f16_ss(uint32_t d, uint64_t a, uint64_t b,
                                           uint32_t idesc, uint32_t en) {
    asm volatile(
        "{\n\t.reg .pred p;\n\tsetp.ne.u32 p, %5, 0;\n\t"
        "tcgen05.mma.cta_group::1.kind::f16 [%0], %1, %2, %3, {%4, %4, %4, %4}, p;\n\t}"
        :: "r"(d), "l"(a), "l"(b), "r"(idesc), "r"(0u), "r"(en) : "memory");
}
__device__ __forceinline__ void tc_commit(uint32_t mbar) {
    asm volatile(
        "tcgen05.commit.cta_group::1.mbarrier::arrive::one.shared::cluster.b64 [%0];"
        :: "r"(mbar) : "memory");
}
__device__ __forceinline__ void ldtm32(uint32_t* r, uint32_t addr) {
    asm volatile(
        "tcgen05.ld.sync.aligned.32x32b.x32.b32 "
        "{%0, %1, %2, %3, %4, %5, %6, %7, "
        " %8, %9, %10, %11, %12, %13, %14, %15, "
        " %16, %17, %18, %19, %20, %21, %22, %23, "
        " %24, %25, %26, %27, %28, %29, %30, %31}, [%32];"
        : "=r"(r[0]),  "=r"(r[1]),  "=r"(r[2]),  "=r"(r[3]),
          "=r"(r[4]),  "=r"(r[5]),  "=r"(r[6]),  "=r"(r[7]),
          "=r"(r[8]),  "=r"(r[9]),  "=r"(r[10]), "=r"(r[11]),
          "=r"(r[12]), "=r"(r[13]), "=r"(r[14]), "=r"(r[15]),
          "=r"(r[16]), "=r"(r[17]), "=r"(r[18]), "=r"(r[19]),
          "=r"(r[20]), "=r"(r[21]), "=r"(r[22]), "=r"(r[23]),
          "=r"(r[24]), "=r"(r[25]), "=r"(r[26]), "=r"(r[27]),
          "=r"(r[28]), "=r"(r[29]), "=r"(r[30]), "=r"(r[31])
        : "r"(addr));
    asm volatile("tcgen05.wait::ld.sync.aligned;" ::: "memory");
}
#endif

// ---------------- convert kernels ----------------
__global__ void __launch_bounds__(256) aconv(const float4* __restrict__ a,
                                             __nv_bfloat162* __restrict__ hi,
                                             __nv_bfloat162* __restrict__ lo, int n4) {
    int i = blockIdx.x * 256 + threadIdx.x;
    if (i >= n4) return;
    float4 v = a[i];
    __nv_bfloat16 h0 = __float2bfloat16(v.x), h1 = __float2bfloat16(v.y);
    __nv_bfloat16 h2 = __float2bfloat16(v.z), h3 = __float2bfloat16(v.w);
    hi[2*i]   = __halves2bfloat162(h0, h1);
    hi[2*i+1] = __halves2bfloat162(h2, h3);
    lo[2*i]   = __halves2bfloat162(__float2bfloat16(v.x - __bfloat162float(h0)),
                                   __float2bfloat16(v.y - __bfloat162float(h1)));
    lo[2*i+1] = __halves2bfloat162(__float2bfloat16(v.z - __bfloat162float(h2)),
                                   __float2bfloat16(v.w - __bfloat162float(h3)));
}

__global__ void __launch_bounds__(256) wconv_all(
        const float* __restrict__ Wq, const float* __restrict__ Wk,
        const float* __restrict__ Wv, const float* __restrict__ Wm,
        const float* __restrict__ W1, const float* __restrict__ W2) {
    int i = blockIdx.x * 256 + threadIdx.x;
    if (i >= 655360) return;
    const float* W; __nv_bfloat16 *hi, *lo; int K, N, li = i;
    if (li < 65536)                { W = Wq; hi = g_wqh;          lo = g_wql;          K = 256; N = 256; }
    else if ((li -= 65536) < 65536){ W = Wk; hi = g_wkvh;         lo = g_wkvl;         K = 256; N = 256; }
    else if ((li -= 65536) < 65536){ W = Wv; hi = g_wkvh + 65536; lo = g_wkvl + 65536; K = 256; N = 256; }
    else if ((li -= 65536) < 65536){ W = Wm; hi = g_wmh;          lo = g_wml;          K = 256; N = 256; }
    else if ((li -= 65536) < 262144){ W = W1; hi = g_w1h;         lo = g_w1l;          K = 512; N = 512; }
    else { li -= 262144;             W = W2; hi = g_w2h;          lo = g_w2l;          K = 512; N = 256; }
    int n = li / K, k = li % K;
    float v = W[(size_t)k * N + n];
    __nv_bfloat16 h = __float2bfloat16(v);
    hi[li] = h;
    lo[li] = __float2bfloat16(v - __bfloat162float(h));
}

// xb -> copy to dst + hcat base halves of TWO consecutive sets (pitch 512)
__global__ void __launch_bounds__(256) prep_base2(const float4* __restrict__ xb,
                                                  float4* __restrict__ dst,
                                                  __nv_bfloat16* __restrict__ hhiA,
                                                  __nv_bfloat16* __restrict__ hloA,
                                                  __nv_bfloat16* __restrict__ hhiB,
                                                  __nv_bfloat16* __restrict__ hloB) {
    int i = blockIdx.x * 256 + threadIdx.x;
    if (i >= ROWS * 64) return;
    float4 v = xb[i];
    dst[i] = v;
    int row = i >> 6, j = i & 63;
    size_t o = (size_t)row * 512 + j * 4;
    float vv[4] = {v.x, v.y, v.z, v.w};
    #pragma unroll
    for (int e = 0; e < 4; e++) {
        __nv_bfloat16 h = __float2bfloat16(vv[e]);
        __nv_bfloat16 l = __float2bfloat16(vv[e] - __bfloat162float(h));
        hhiA[o + e] = h; hloA[o + e] = l;
        hhiB[o + e] = h; hloB[o + e] = l;
    }
}

// ---------------- tcgen05 GEMM, BK=32/SW64, 2 CTAs/SM, smem-staged epilogue ----------------
// EPI 0: fp32 -> Cf (or Cf2 when bn >= nsplit) ; EPI 1: relu -> bf16 hi/lo ;
// EPI 2: LN -> bf16 hi/lo at coff ; EPI 3: atomicAdd(Cf, 0.5*LN) with row mod rowmod
template<int EPI>
__global__ void __launch_bounds__(256, 2) tc_gemm(
        const __grid_constant__ CUtensorMap mAh, const __grid_constant__ CUtensorMap mAl,
        const __grid_constant__ CUtensorMap mBh, const __grid_constant__ CUtensorMap mBl,
        const __nv_bfloat16* __restrict__ Ahi, const __nv_bfloat16* __restrict__ Alo,
        const __nv_bfloat16* __restrict__ Bhi, const __nv_bfloat16* __restrict__ Blo,
        float* __restrict__ Cf, float* __restrict__ Cf2,
        __nv_bfloat16* __restrict__ Chi, __nv_bfloat16* __restrict__ Clo,
        const float* __restrict__ Gw, const float* __restrict__ Bw,
        int K, int ldc, int coff, int rowmod, int nsplit) {
#if HAS_TCGEN05
    extern __shared__ char dsm_raw[];
    char* sbase = (char*)(((uintptr_t)dsm_raw + 1023) & ~(uintptr_t)1023);
    __shared__ uint32_t s_tmem;
    __shared__ __align__(8) unsigned long long s_mbar[4];
    const uint32_t mb = smem_u32(s_mbar);
    const int t = threadIdx.x, wid = t >> 5, lane = t & 31;

    if (wid == 0) {
        asm volatile("tcgen05.alloc.cta_group::1.sync.aligned.shared::cta.b32 [%0], %1;"
                     :: "r"(smem_u32(&s_tmem)), "r"(256u) : "memory");
        asm volatile("tcgen05.relinquish_alloc_permit.cta_group::1.sync.aligned;");
    }
    if (t == 0) {
        mbar_init(mb, 1); mbar_init(mb + 8, 1);
        mbar_init(mb + 16, 1); mbar_init(mb + 24, 1);
    }
    __syncthreads();
    const uint32_t tmem = s_tmem;

    const int bm = blockIdx.y * BM, bn = blockIdx.x * BN;
    const int NC = K >> 5;
    const uint32_t idesc = (1u << 4) | (1u << 7) | (1u << 10)
                         | ((BN / 8) << 17) | ((BM / 16) << 24);
    const uint32_t sb32 = smem_u32(sbase);

    if (t == 0) {
        mbar_expect_tx(mb, STAGE_BYTES);
        tma2d(sb32 + A_HI, &mAh, 0, bm, mb);
        tma2d(sb32 + A_LO, &mAl, 0, bm, mb);
        tma2d(sb32 + B_HI, &mBh, 0, bn, mb);
        tma2d(sb32 + B_LO, &mBl, 0, bn, mb);
        if (NC > 1) {
            uint32_t st = sb32 + STAGE_BYTES;
            mbar_expect_tx(mb + 8, STAGE_BYTES);
            tma2d(st + A_HI, &mAh, BK, bm, mb + 8);
            tma2d(st + A_LO, &mAl, BK, bm, mb + 8);
            tma2d(st + B_HI, &mBh, BK, bn, mb + 8);
            tma2d(st + B_LO, &mBl, BK, bn, mb + 8);
        }
        int fph[2] = {0, 0}, mph[2] = {0, 0}, pend[2] = {0, 0};
        for (int c = 0; c < NC; c++) {
            const int s = c & 1;
            mbar_wait(mb + s * 8, fph[s]); fph[s] ^= 1;
            uint32_t st = sb32 + s * STAGE_BYTES;
            uint64_t dAh = make_desc64(st + A_HI), dAl = make_desc64(st + A_LO);
            uint64_t dBh = make_desc64(st + B_HI), dBl = make_desc64(st + B_LO);
            #pragma unroll
            for (int kk2 = 0; kk2 < 2; kk2++) {
                mma_f16_ss(tmem, dAh + kk2 * 2, dBh + kk2 * 2, idesc, (c > 0) || (kk2 > 0));
                mma_f16_ss(tmem, dAh + kk2 * 2, dBl + kk2 * 2, idesc, 1u);
                mma_f16_ss(tmem, dAl + kk2 * 2, dBh + kk2 * 2, idesc, 1u);
            }
            tc_commit(mb + 16 + s * 8);
            pend[s] = 1;
            if (c + 2 < NC) {
                mbar_wait(mb + 16 + s * 8, mph[s]); mph[s] ^= 1; pend[s] = 0;
                int k0 = (c + 2) * BK;
                mbar_expect_tx(mb + s * 8, STAGE_BYTES);
                tma2d(st + A_HI, &mAh, k0, bm, mb + s * 8);
                tma2d(st + A_LO, &mAl, k0, bm, mb + s * 8);
                tma2d(st + B_HI, &mBh, k0, bn, mb + s * 8);
                tma2d(st + B_LO, &mBl, k0, bn, mb + s * 8);
            }
        }
        if (pend[0]) mbar_wait(mb + 16, mph[0]);
        if (pend[1]) mbar_wait(mb + 24, mph[1]);
    }
    __syncthreads();
    asm volatile("tcgen05.fence::after_thread_sync;" ::: "memory");

    // smem-staged, coalesced epilogue
    float* Co = Cf;
    int bnc = bn;
    if (EPI == 0 && nsplit && bn >= nsplit) { Co = Cf2; bnc = bn - nsplit; }

    float (*tile)[33] = (float(*)[33])sbase;
    float mean = 0.f, rstd = 0.f;
    if (EPI >= 2 && wid < 4) {
        float s = 0.f, s2 = 0.f;
        #pragma unroll
        for (int ch = 0; ch < 8; ch++) {
            uint32_t r[32];
            ldtm32(r, tmem + ch * 32);
            #pragma unroll
            for (int j = 0; j < 32; j++) {
                float v = __uint_as_float(r[j]);
                s += v; s2 += v * v;
            }
        }
        mean = s * (1.f / 256.f);
        float var = fmaf(-mean, mean, s2 * (1.f / 256.f));
        rstd = rsqrtf(var + 1e-5f);
    }
    #pragma unroll
    for (int ch = 0; ch < 8; ch++) {
        if (wid < 4) {
            uint32_t r[32];
            ldtm32(r, tmem + ch * 32);
            int rloc = wid * 32 + lane;
            #pragma unroll
            for (int j = 0; j < 32; j++) {
                float v = __uint_as_float(r[j]);
                if (EPI == 1) v = fmaxf(v, 0.f);
                if (EPI >= 2) {
                    int col = ch * 32 + j;
                    v = (v - mean) * rstd * Gw[col] + Bw[col];
                    if (EPI == 3) v *= 0.5f;
                }
                tile[rloc][j] = v;
            }
        }
        __syncthreads();
        #pragma unroll
        for (int i = 0; i < 16; i++) {
            int idx = i * 256 + t;
            int rr = idx >> 5, cc = idx & 31;
            float v = tile[rr][cc];
            int orow = bm + rr;
            if (EPI == 3 && orow >= rowmod) orow -= rowmod;
            size_t ro = (size_t)orow * ldc + bnc + coff + ch * 32 + cc;
            if (EPI == 0)       Co[ro] = v;
            else if (EPI == 3)  atomicAdd(Cf + ro, v);
            else                split_store(Chi, Clo, ro, v);
        }
        __syncthreads();
    }
    if (wid == 0)
        asm volatile("tcgen05.dealloc.cta_group::1.sync.aligned.b32 %0, %1;"
                     :: "r"(tmem), "r"(256u));
#else
    // compile-only fallback (never runs on GB300)
    const int bm = blockIdx.y * BM, bn = blockIdx.x * BN;
    const int t = threadIdx.x;
    if (t < BM) {
        int row = bm + t;
        float vals[BN];
        for (int c = 0; c < BN; c++) {
            const __nv_bfloat16* ah = Ahi + (size_t)row * K;
            const __nv_bfloat16* al = Alo + (size_t)row * K;
            const __nv_bfloat16* bh = Bhi + (size_t)(bn + c) * K;
            const __nv_bfloat16* bl = Blo + (size_t)(bn + c) * K;
            float acc = 0.f;
            for (int kk = 0; kk < K; kk++)
                acc += (__bfloat162float(ah[kk]) + __bfloat162float(al[kk])) *
                       (__bfloat162float(bh[kk]) + __bfloat162float(bl[kk]));
            vals[c] = acc;
        }
        float mean = 0.f, rstd = 1.f;
        if (EPI >= 2) {
            float s = 0.f, s2 = 0.f;
            for (int c = 0; c < BN; c++) { s += vals[c]; s2 += vals[c] * vals[c]; }
            mean = s / BN;
            rstd = rsqrtf(s2 / BN - mean * mean + 1e-5f);
        }
        float* Co = Cf;
        int bnc = bn;
        if (EPI == 0 && nsplit && bn >= nsplit) { Co = Cf2; bnc = bn - nsplit; }
        for (int c = 0; c < BN; c++) {
            float v = vals[c];
            if (EPI == 1) v = fmaxf(v, 0.f);
            if (EPI >= 2) { v = (v - mean) * rstd * Gw[c] + Bw[c]; if (EPI == 3) v *= 0.5f; }
            int orow = row;
            if (EPI == 3 && orow >= rowmod) orow -= rowmod;
            size_t ro = (size_t)orow * ldc + bnc + coff + c;
            if (EPI == 0)      Co[ro] = v;
            else if (EPI == 3) atomicAdd(Cf + ro, v);
            else               split_store(Chi, Clo, ro, v);
        }
    }
#endif
}

// ---------------- coalesced permutes ----------------
__global__ void __launch_bounds__(256) perm13(const float* q, const float* k, const float* v,
                                              float* qd, float* kd, float* vd) {
    __shared__ float s[8][256];
    const float* S = blockIdx.z == 0 ? q : (blockIdx.z == 1 ? k : v);
    float* Dd = blockIdx.z == 0 ? qd : (blockIdx.z == 1 ? kd : vd);
    size_t rowbase = (size_t)blockIdx.x * 8;
    int t = threadIdx.x;
    #pragma unroll
    for (int i = 0; i < 8; i++) s[i][t] = S[(rowbase + i) * 256 + t];
    __syncthreads();
    int c0 = (t & 7) * 32 + (t >> 3);
    #pragma unroll
    for (int i = 0; i < 8; i++) Dd[(rowbase + i) * 256 + t] = s[i][c0];
}

__global__ void __launch_bounds__(256) perm32(const float* q, const float* k, const float* v,
                                              float* qd, float* kd, float* vd) {
    __shared__ float sm[32][33];
    const float* S = blockIdx.z == 0 ? q : (blockIdx.z == 1 ? k : v);
    float* Dd = blockIdx.z == 0 ? qd : (blockIdx.z == 1 ? kd : vd);
    int b = blockIdx.y;
    int l0b = blockIdx.x * 32;
    size_t bo = (size_t)b * BSTRIDE;
    int wr = threadIdx.x >> 5, lane = threadIdx.x & 31;
    for (int h0 = 0; h0 < H; h0++) {
        #pragma unroll
        for (int it = 0; it < 4; it++) {
            int row = wr + it * 8;
            sm[row][lane] = S[bo + (size_t)(l0b + row) * 256 + h0 * 32 + lane];
        }
        __syncthreads();
        #pragma unroll
        for (int it = 0; it < 4; it++) {
            int d0 = wr + it * 8;
            Dd[bo + (size_t)d0 * 38400 + h0 * 4800 + l0b + lane] = sm[lane][d0];
        }
        __syncthreads();
    }
}

// ---------------- KV reduce, ONE set ----------------
#define KVSPLIT 10
#define KVCHUNK (LL/KVSPLIT)
__global__ void __launch_bounds__(256) kv_one(
        const float* __restrict__ kk, const float* __restrict__ vv,
        float* __restrict__ kvz, int m21) {
    int b = blockIdx.x >> 3, h = blockIdx.x & 7;
    int sbeg = blockIdx.y * KVCHUNK;
    const float* kb = kk + (size_t)b * BSTRIDE;
    const float* vb = vv + (size_t)b * BSTRIDE;
    __shared__ float ks[8][32], vs[8][32];
    int t = threadIdx.x;
    int r = t >> 5, c = t & 31;
    float acc[4] = {0.f, 0.f, 0.f, 0.f};
    float ksacc = 0.f;
    for (int s0 = sbeg; s0 < sbeg + KVCHUNK; s0 += 8) {
        int off = m21 ? off21(s0 + r, h * DH + c) : (s0 + r) * 256 + h * DH + c;
        ks[r][c] = phi(kb[off]);
        vs[r][c] = vb[off];
        __syncthreads();
        #pragma unroll
        for (int row = 0; row < 8; row++) {
            float ve = vs[row][c];
            #pragma unroll
            for (int jj = 0; jj < 4; jj++)
                acc[jj] += ks[row][r + jj * 8] * ve;
        }
        if (t < 32) {
            #pragma unroll
            for (int row = 0; row < 8; row++) ksacc += ks[row][t];
        }
        __syncthreads();
    }
    float* kvout = kvz + (size_t)(b * H + h) * DH * DH;
    #pragma unroll
    for (int jj = 0; jj < 4; jj++)
        atomicAdd(&kvout[(r + jj * 8) * DH + c], acc[jj]);
    if (t < 32) atomicAdd(&kvz[BS*H*DH*DH + (b * H + h) * DH + t], ksacc);
}

// ---------------- attention apply, ONE set ----------------
__global__ void __launch_bounds__(256) attn_one(
        const float* __restrict__ qsel, const float* __restrict__ kvz,
        __nv_bfloat16* __restrict__ mhi, __nv_bfloat16* __restrict__ mlo, int m21) {
    extern __shared__ float as_[];
    float* sKV = as_;
    float* sKs = sKV + H * DH * DH;
    float (*sQ)[256] = (float(*)[256])(sKs + H * DH);
    float* sZ = (float*)(sQ + ATOK);
    int b  = blockIdx.y;
    int l0 = blockIdx.x * ATOK;
    int t = threadIdx.x;
    const float* kvb = kvz + (size_t)b * H * DH * DH;
    #pragma unroll
    for (int i = t; i < H * DH * DH; i += 256) sKV[i] = kvb[i];
    if (t < H * DH) sKs[t] = kvz[BS*H*DH*DH + b * H * DH + t];
    const float* qb = qsel + (size_t)b * BSTRIDE;
    #pragma unroll
    for (int i = 0; i < ATOK; i++) {
        int off = m21 ? off21(l0 + i, t) : (l0 + i) * 256 + t;
        sQ[i][t] = phi(qb[off]);
    }
    __syncthreads();
    {
        int tok = t >> 3, h = t & 7;
        float z = 0.f;
        #pragma unroll
        for (int d = 0; d < DH; d++) z += sQ[tok][h * DH + d] * sKs[h * DH + d];
        sZ[tok * H + h] = 1.f / (z + 1e-6f);
    }
    __syncthreads();
    int c = t, h = c >> 5, e = c & 31;
    float kvreg[DH];
    #pragma unroll
    for (int d = 0; d < DH; d++) kvreg[d] = sKV[(h * DH + d) * DH + e];
    size_t base = (size_t)b * BSTRIDE + (size_t)l0 * D;
    #pragma unroll 4
    for (int jj = 0; jj < ATOK; jj++) {
        float dot = 0.f;
        #pragma unroll
        for (int d = 0; d < DH; d++)
            dot += sQ[jj][h * DH + d] * kvreg[d];
        split_store(mhi, mlo, base + (size_t)jj * D + c, dot * sZ[jj * H + h]);
    }
}

// ---------------- host orchestration ----------------
typedef CUresult (*EncFn)(CUtensorMap*, CUtensorMapDataType, cuuint32_t, void*,
        const cuuint64_t*, const cuuint64_t*, const cuuint32_t*, const cuuint32_t*,
        CUtensorMapInterleave, CUtensorMapSwizzle, CUtensorMapL2promotion,
        CUtensorMapFloatOOBfill);

extern "C" void kernel_launch(void* const* d_in, const int* in_sizes, int n_in,
                              void* d_out, int out_size) {
    (void)in_sizes; (void)n_in; (void)out_size;
    const float* x   = (const float*)d_in[0];
    const float* src = (const float*)d_in[1];
    const float* Wq  = (const float*)d_in[2];
    const float* Wk  = (const float*)d_in[3];
    const float* Wv  = (const float*)d_in[4];
    const float* Wm  = (const float*)d_in[5];
    const float* W1  = (const float*)d_in[6];
    const float* W2  = (const float*)d_in[7];
    const float* g1  = (const float*)d_in[8];
    const float* b1  = (const float*)d_in[9];
    const float* g2  = (const float*)d_in[10];
    const float* b2  = (const float*)d_in[11];
    float* out = (float*)d_out;

    float *q, *k, *v, *qp1, *kp1, *vp1, *qp2, *kp2, *vp2, *xmid, *kvz;
    cudaGetSymbolAddress((void**)&q,    g_q);
    cudaGetSymbolAddress((void**)&k,    g_k);
    cudaGetSymbolAddress((void**)&v,    g_v);
    cudaGetSymbolAddress((void**)&qp1,  g_qp1);
    cudaGetSymbolAddress((void**)&kp1,  g_kp1);
    cudaGetSymbolAddress((void**)&vp1,  g_vp1);
    cudaGetSymbolAddress((void**)&qp2,  g_qp2);
    cudaGetSymbolAddress((void**)&kp2,  g_kp2);
    cudaGetSymbolAddress((void**)&vp2,  g_vp2);
    cudaGetSymbolAddress((void**)&xmid, g_xmid);
    cudaGetSymbolAddress((void**)&kvz,  g_kvz);

    __nv_bfloat16 *mhi, *mlo, *hhi, *hlo, *thi, *tlo;
    cudaGetSymbolAddress((void**)&mhi, g_mhi); cudaGetSymbolAddress((void**)&mlo, g_mlo);
    cudaGetSymbolAddress((void**)&hhi, g_hhi); cudaGetSymbolAddress((void**)&hlo, g_hlo);
    cudaGetSymbolAddress((void**)&thi, g_thi); cudaGetSymbolAddress((void**)&tlo, g_tlo);

    __nv_bfloat16 *wqh, *wql, *wkvh, *wkvl, *wmh, *wml, *w1h, *w1l, *w2h, *w2l;
    cudaGetSymbolAddress((void**)&wqh, g_wqh);   cudaGetSymbolAddress((void**)&wql, g_wql);
    cudaGetSymbolAddress((void**)&wkvh, g_wkvh); cudaGetSymbolAddress((void**)&wkvl, g_wkvl);
    cudaGetSymbolAddress((void**)&wmh, g_wmh);   cudaGetSymbolAddress((void**)&wml, g_wml);
    cudaGetSymbolAddress((void**)&w1h, g_w1h);   cudaGetSymbolAddress((void**)&w1l, g_w1l);
    cudaGetSymbolAddress((void**)&w2h, g_w2h);   cudaGetSymbolAddress((void**)&w2l, g_w2l);

    EncFn enc = nullptr;
    {
        void* fp = nullptr;
#if CUDART_VERSION >= 12050
        cudaDriverEntryPointQueryResult qr;
        cudaGetDriverEntryPoint("cuTensorMapEncodeTiled", &fp, cudaEnableDefault, &qr);
#else
        cudaGetDriverEntryPoint("cuTensorMapEncodeTiled", &fp, cudaEnableDefault);
#endif
        enc = (EncFn)fp;
    }
    auto mk = [&](void* ptr, uint64_t k_elems, uint64_t rows, uint32_t boxrows) {
        CUtensorMap m{};
        cuuint64_t dims[2] = {k_elems, rows};
        cuuint64_t strides[1] = {k_elems * 2};
        cuuint32_t box[2] = {32, boxrows};
        cuuint32_t es[2] = {1, 1};
        enc(&m, CU_TENSOR_MAP_DATA_TYPE_BFLOAT16, 2, ptr, dims, strides, box, es,
            CU_TENSOR_MAP_INTERLEAVE_NONE, CU_TENSOR_MAP_SWIZZLE_64B,
            CU_TENSOR_MAP_L2_PROMOTION_L2_128B, CU_TENSOR_MAP_FLOAT_OOB_FILL_NONE);
        return m;
    };
    // per-set A maps
    CUtensorMap tm_m[4], tm_ml_[4], tm_h[4], tm_hl_[4];
    for (int i = 0; i < 4; i++) {
        tm_m[i]   = mk(mhi + (size_t)i*ROWS*D, 256, ROWS, 128);
        tm_ml_[i] = mk(mlo + (size_t)i*ROWS*D, 256, ROWS, 128);
        tm_h[i]   = mk(hhi + (size_t)i*ROWS*512, 512, ROWS, 128);
        tm_hl_[i] = mk(hlo + (size_t)i*ROWS*512, 512, ROWS, 128);
    }
    CUtensorMap tm_tA  = mk(thi, 512, ROWS, 128);
    CUtensorMap tm_tAl = mk(tlo, 512, ROWS, 128);
    CUtensorMap tm_tB  = mk(thi + (size_t)ROWS*512, 512, ROWS, 128);
    CUtensorMap tm_tBl = mk(tlo + (size_t)ROWS*512, 512, ROWS, 128);
    CUtensorMap tm_wqh = mk(wqh, 256, 256, 256), tm_wql = mk(wql, 256, 256, 256);
    CUtensorMap tm_wkv = mk(wkvh, 256, 512, 256), tm_wkvl = mk(wkvl, 256, 512, 256);
    CUtensorMap tm_wmh = mk(wmh, 256, 256, 256), tm_wml = mk(wml, 256, 256, 256);
    CUtensorMap tm_w1h = mk(w1h, 512, 512, 256), tm_w1l = mk(w1l, 512, 512, 256);
    CUtensorMap tm_w2h = mk(w2h, 512, 256, 256), tm_w2l = mk(w2l, 512, 256, 256);

    cudaFuncSetAttribute(tc_gemm<0>, cudaFuncAttributeMaxDynamicSharedMemorySize, SMEM_DYN);
    cudaFuncSetAttribute(tc_gemm<1>, cudaFuncAttributeMaxDynamicSharedMemorySize, SMEM_DYN);
    cudaFuncSetAttribute(tc_gemm<2>, cudaFuncAttributeMaxDynamicSharedMemorySize, SMEM_DYN);
    cudaFuncSetAttribute(tc_gemm<3>, cudaFuncAttributeMaxDynamicSharedMemorySize, SMEM_DYN);
    const int ATTN_SMEM = (H*DH*DH + H*DH + ATOK*256 + ATOK*H) * 4;
    cudaFuncSetAttribute(attn_one, cudaFuncAttributeMaxDynamicSharedMemorySize, ATTN_SMEM);

    static cudaStream_t s1 = nullptr, s2 = nullptr;
    static cudaEvent_t ev[10];
    if (!s1) {
        cudaStreamCreateWithFlags(&s1, cudaStreamNonBlocking);
        cudaStreamCreateWithFlags(&s2, cudaStreamNonBlocking);
        for (int i = 0; i < 10; i++)
            cudaEventCreateWithFlags(&ev[i], cudaEventDisableTiming);
    }
    cudaEvent_t evW = ev[0], evQ = ev[1], evKV = ev[2], evPrep1 = ev[3],
                evX1 = ev[4], evX2 = ev[5], evPrep2 = ev[6],
                evO1 = ev[7], evO2 = ev[8];

    dim3 thr(256);

    // per-set chain helpers (kernel shapes per single set)
    auto attn_chain = [&](cudaStream_t st, int si, const float* qq,
                          const float* kk, const float* vv, int m21) {
        cudaMemsetAsync(kvz + (size_t)si * KVN, 0, (size_t)KVN * sizeof(float), st);
        kv_one<<<dim3(BS*H, KVSPLIT), thr, 0, st>>>(kk, vv, kvz + (size_t)si * KVN, m21);
        attn_one<<<dim3(LL/ATOK, BS), thr, ATTN_SMEM, st>>>(qq, kvz + (size_t)si * KVN,
                mhi + (size_t)si*ROWS*D, mlo + (size_t)si*ROWS*D, m21);
        tc_gemm<2><<<dim3(1, ROWS/BM), thr, SMEM_DYN, st>>>(tm_m[si], tm_ml_[si],
                tm_wmh, tm_wml,
                mhi + (size_t)si*ROWS*D, mlo + (size_t)si*ROWS*D, wmh, wml,
                nullptr, nullptr, hhi + (size_t)si*ROWS*512, hlo + (size_t)si*ROWS*512,
                g1, b1, D, 2*D, D, 0, 0);
    };
    auto mlp_chain = [&](cudaStream_t st, int si, float* accbuf,
                         __nv_bfloat16* Sthi, __nv_bfloat16* Stlo,
                         CUtensorMap& tmt_h, CUtensorMap& tmt_l) {
        tc_gemm<1><<<dim3(2, ROWS/BM), thr, SMEM_DYN, st>>>(tm_h[si], tm_hl_[si],
                tm_w1h, tm_w1l,
                hhi + (size_t)si*ROWS*512, hlo + (size_t)si*ROWS*512, w1h, w1l,
                nullptr, nullptr, Sthi, Stlo, nullptr, nullptr, 2*D, 2*D, 0, 0, 0);
        tc_gemm<3><<<dim3(1, ROWS/BM), thr, SMEM_DYN, st>>>(tmt_h, tmt_l, tm_w2h, tm_w2l,
                Sthi, Stlo, w2h, w2l, accbuf, nullptr, nullptr, nullptr, g2, b2,
                2*D, D, 0, ROWS, 0);
    };

    // root
    wconv_all<<<2560, thr>>>(Wq, Wk, Wv, Wm, W1, W2);
    cudaEventRecord(evW, 0);
    prep_base2<<<ROWS*64/256, thr>>>((const float4*)x, (float4*)xmid,
            hhi, hlo, hhi + (size_t)ROWS*512, hlo + (size_t)ROWS*512);
    cudaEventRecord(evPrep1, 0);
    cudaStreamWaitEvent(s1, evW, 0);
    cudaStreamWaitEvent(s2, evW, 0);

    // s1: aconv(x into m set0 slot) + Wq
    aconv<<<ROWS*D/4/256, thr, 0, s1>>>((const float4*)x,
            (__nv_bfloat162*)mhi, (__nv_bfloat162*)mlo, ROWS*D/4);
    tc_gemm<0><<<dim3(1, ROWS/BM), thr, SMEM_DYN, s1>>>(tm_m[0], tm_ml_[0], tm_wqh, tm_wql,
            mhi, mlo, wqh, wql, q, nullptr, nullptr, nullptr, nullptr, nullptr,
            D, D, 0, 0, 0);
    cudaEventRecord(evQ, s1);

    // s2: aconv(src into m set1 slot) + merged Wk|Wv
    aconv<<<ROWS*D/4/256, thr, 0, s2>>>((const float4*)src,
            (__nv_bfloat162*)(mhi + (size_t)ROWS*D), (__nv_bfloat162*)(mlo + (size_t)ROWS*D),
            ROWS*D/4);
    tc_gemm<0><<<dim3(2, ROWS/BM), thr, SMEM_DYN, s2>>>(tm_m[1], tm_ml_[1], tm_wkv, tm_wkvl,
            mhi + (size_t)ROWS*D, mlo + (size_t)ROWS*D, wkvh, wkvl,
            k, v, nullptr, nullptr, nullptr, nullptr, D, D, 0, 0, 256);
    cudaEventRecord(evKV, s2);

    // ---- s1: set0 (mode0) attn chain -> phase1 MLP set0 ----
    cudaStreamWaitEvent(s1, evKV, 0);
    attn_chain(s1, 0, q, k, v, 0);
    cudaStreamWaitEvent(s1, evPrep1, 0);
    mlp_chain(s1, 0, xmid, thi, tlo, tm_tA, tm_tAl);
    cudaEventRecord(evX1, s1);

    // ---- s2: set1 (perm13) attn chain -> phase1 MLP set1 ----
    cudaStreamWaitEvent(s2, evQ, 0);
    perm13<<<dim3(ROWS/8, 1, 3), thr, 0, s2>>>(q, k, v, qp1, kp1, vp1);
    attn_chain(s2, 1, qp1, kp1, vp1, 0);
    cudaStreamWaitEvent(s2, evPrep1, 0);
    mlp_chain(s2, 1, xmid, thi + (size_t)ROWS*512, tlo + (size_t)ROWS*512, tm_tB, tm_tBl);
    cudaEventRecord(evX2, s2);

    // ---- s1: set2 (mode21) attn chain (overlaps join/prep2) ----
    attn_chain(s1, 2, q, k, v, 1);

    // ---- s2: set3 (perm32) attn chain ----
    perm32<<<dim3(150, BS, 3), thr, 0, s2>>>(q, k, v, qp2, kp2, vp2);
    attn_chain(s2, 3, qp2, kp2, vp2, 0);

    // ---- join: prep2 (out = xmid; base halves sets 2,3) ----
    cudaStreamWaitEvent(0, evX1, 0);
    cudaStreamWaitEvent(0, evX2, 0);
    prep_base2<<<ROWS*64/256, thr>>>((const float4*)xmid, (float4*)out,
            hhi + (size_t)2*ROWS*512, hlo + (size_t)2*ROWS*512,
            hhi + (size_t)3*ROWS*512, hlo + (size_t)3*ROWS*512);
    cudaEventRecord(evPrep2, 0);

    // ---- phase2 MLP: set2 on s1, set3 on s2 ----
    cudaStreamWaitEvent(s1, evPrep2, 0);
    mlp_chain(s1, 2, out, thi, tlo, tm_tA, tm_tAl);
    cudaEventRecord(evO1, s1);
    cudaStreamWaitEvent(s2, evPrep2, 0);
    mlp_chain(s2, 3, out, thi + (size_t)ROWS*512, tlo + (size_t)ROWS*512, tm_tB, tm_tBl);
    cudaEventRecord(evO2, s2);

    // final join
    cudaStreamWaitEvent(0, evO1, 0);
    cudaStreamWaitEvent(0, evO2, 0);
}